// round 6
// baseline (speedup 1.0000x reference)
#include <cuda_runtime.h>
#include <cstdint>

#define T_LEN   32768
#define B_SZ    4
#define HID     128
#define NL      4
#define KERS    3
#define CONDC   512
#define LC      128
#define HOPSZ   256
#define LAYER_R 49152   /* HID*HID*KERS */

// ---------------- scratch (device globals; no allocation) ----------------
static __device__ float g_kallp[(size_t)B_SZ * LC * LAYER_R]; // 100.7 MB, per-layer reuse
static __device__ float g_hA[(size_t)B_SZ * HID * T_LEN];     // 64 MB
static __device__ float g_hB[(size_t)B_SZ * HID * T_LEN];     // 64 MB
static __device__ float g_ballT[B_SZ * LC * 512];             // 1 MB  [b][l][layer*128+o]
static __device__ float g_wT[NL * HID * KERS * HID];          // 0.75 MB [layer][i][k][o]

// ---------------- tiny setup: permute dilated-conv weights ----------------
// block_w: (layer, o, i, k) -> g_wT: (layer, i, k, o)
__global__ void k_permw(const float* __restrict__ bw) {
    int s = blockIdx.x * 256 + threadIdx.x;
    if (s >= NL * HID * HID * KERS) return;
    int k = s % 3; int q = s / 3;
    int i = q % 128; q /= 128;
    int o = q % 128; int layer = q / 128;
    g_wT[((layer * 128 + i) * 3 + k) * 128 + o] = bw[s];
}

// ---------------- preconv: h = leaky(pre_w*x + pre_b, 0.2) ----------------
__global__ void k_pre(const float* __restrict__ x, const float* __restrict__ pw,
                      const float* __restrict__ pb) {
    const int bc = blockIdx.y;                  // b*128 + ch
    const int t  = blockIdx.x * 256 + threadIdx.x;
    const int b  = bc >> 7, ch = bc & 127;
    float v = pw[ch] * x[(long)b * T_LEN + t] + pb[ch];
    v = v >= 0.f ? v : 0.2f * v;
    g_hA[(long)bc * T_LEN + t] = v;
}

// ---------------- bias predictor: g_ballT[b][l][row] ----------------
__global__ void k_biasp(const float* __restrict__ bw, const float* __restrict__ bb,
                        const float* __restrict__ cc) {
    const int row = blockIdx.x, b = blockIdx.y;
    const int l = threadIdx.x;                  // 128 threads
    const float* cp = cc + (long)b * CONDC * LC + l;
    const float* wp = bw + (long)row * CONDC;
    float acc = bb[row];
#pragma unroll 8
    for (int c2 = 0; c2 < CONDC; c2++) acc += wp[c2] * cp[(long)c2 * LC];
    g_ballT[((long)(b * LC + l)) * 512 + row] = acc;
}

// ---------------- kernel-predictor GEMM (one layer) ----------------
// For permuted row r' = (i*3+k)*128 + o within this layer:
//   g_kallp[b][l][r'] = sum_c kernel_w[orig_r][c]*c[b][c][l] + kernel_b[orig_r]
// where orig_r = ((layer*128+i)*128+o)*3+k.  M-tile m covers fixed (i,k), o = rr.
__global__ void __launch_bounds__(256, 2)
k_gemm_pred(const float* __restrict__ kw, const float* __restrict__ kb,
            const float* __restrict__ cc, int layer) {
    const int b = blockIdx.x;
    const int m = blockIdx.y;                   // 0..383
    const int ic  = m / 3;
    const int kof = m - ic * 3;
    const long rowbase = ((long)(layer * HID + ic) * HID) * KERS + kof; // + 3*rr

    __shared__ __align__(16) float As[16][132]; // [k][r]
    __shared__ __align__(16) float Bs[16][128]; // [k][l]

    const int tid = threadIdx.x;
    const int ri = tid & 15, li = tid >> 4;
    const int r0 = ri * 8, l0 = li * 8;

    float acc[8][8];
#pragma unroll
    for (int i = 0; i < 8; i++)
#pragma unroll
        for (int j = 0; j < 8; j++) acc[i][j] = 0.f;

    const float* cb = cc + (long)b * CONDC * LC;

    for (int kt = 0; kt < CONDC; kt += 16) {
        __syncthreads();
#pragma unroll
        for (int it = 0; it < 2; it++) {        // A tile: 128 rows x 16 k
            int f = tid + 256 * it;             // float4 index
            int rr = f >> 2, kq = f & 3;
            float4 v = *(const float4*)(kw + (rowbase + 3L * rr) * CONDC + kt + (kq << 2));
            As[(kq << 2) + 0][rr] = v.x; As[(kq << 2) + 1][rr] = v.y;
            As[(kq << 2) + 2][rr] = v.z; As[(kq << 2) + 3][rr] = v.w;
        }
#pragma unroll
        for (int it = 0; it < 2; it++) {        // B tile: 16 k x 128 l
            int f = tid + 256 * it;
            int kr = f >> 5, lq = f & 31;
            *(float4*)&Bs[kr][lq << 2] = *(const float4*)(cb + (long)(kt + kr) * LC + (lq << 2));
        }
        __syncthreads();
#pragma unroll
        for (int ks = 0; ks < 16; ks++) {
            const float4 a0 = *(const float4*)&As[ks][r0];
            const float4 a1 = *(const float4*)&As[ks][r0 + 4];
            const float4 c0 = *(const float4*)&Bs[ks][l0];
            const float4 c1 = *(const float4*)&Bs[ks][l0 + 4];
            const float av[8] = {a0.x, a0.y, a0.z, a0.w, a1.x, a1.y, a1.z, a1.w};
            const float bv[8] = {c0.x, c0.y, c0.z, c0.w, c1.x, c1.y, c1.z, c1.w};
#pragma unroll
            for (int i = 0; i < 8; i++)
#pragma unroll
                for (int j = 0; j < 8; j++) acc[i][j] += av[i] * bv[j];
        }
    }

    float bias[8];
#pragma unroll
    for (int i = 0; i < 8; i++) bias[i] = kb[rowbase + 3 * (r0 + i)];

#pragma unroll
    for (int lj = 0; lj < 8; lj++) {
        float* dst = g_kallp + ((long)(b * LC + l0 + lj)) * LAYER_R + m * 128 + r0;
        float4 v0, v1;
        v0.x = acc[0][lj] + bias[0]; v0.y = acc[1][lj] + bias[1];
        v0.z = acc[2][lj] + bias[2]; v0.w = acc[3][lj] + bias[3];
        v1.x = acc[4][lj] + bias[4]; v1.y = acc[5][lj] + bias[5];
        v1.z = acc[6][lj] + bias[6]; v1.w = acc[7][lj] + bias[7];
        *(float4*)dst = v0; *(float4*)(dst + 4) = v1;
    }
}

// ---------------- LVC layer: g_hA -> g_hB ----------------
// out[b,o,t0+s] = leaky( sum_{i,k} hA[b,i,t0+s+k-1]*ker[b,l,i,k,o] + bias[b,l,o], 3 )
// Static smem only (<= 48KB): 64-channel input slab, 2 passes.
__global__ void __launch_bounds__(256, 2) k_lvc(int layer) {
    __shared__ __align__(16) float hs[64][132]; // 33.8 KB; cols 0..129 = t0-1..t0+128
    __shared__ __align__(16) float As[24][128]; // 12.3 KB; [(i%8)*3+k][o]

    const int sh = blockIdx.x, l = blockIdx.y, b = blockIdx.z;
    const int t0 = l * HOPSZ + sh * 128;
    const int tid = threadIdx.x;
    const int wid = tid >> 5, lane = tid & 31;
    const long hb = (long)b * HID * T_LEN;

    const float* kerb = g_kallp + ((long)(b * LC + l)) * LAYER_R;
    float acc[8][8];
#pragma unroll
    for (int i = 0; i < 8; i++)
#pragma unroll
        for (int j = 0; j < 8; j++) acc[i][j] = 0.f;

    const int ri = tid & 15, li = tid >> 4;
    const int o0 = ri * 8, s0 = li * 8;

    for (int cpass = 0; cpass < 2; cpass++) {
        __syncthreads();                         // prior pass done reading hs
        const int c0 = cpass * 64;
        for (int i = wid; i < 64; i += 8) {
            const float* src = g_hA + hb + (long)(c0 + i) * T_LEN;
            for (int tt = lane; tt < 130; tt += 32) {
                int t = t0 - 1 + tt;
                hs[i][tt] = (t >= 0 && t < T_LEN) ? src[t] : 0.f;
            }
        }
        for (int it = 0; it < 8; it++) {         // chunks of 8 input channels
            __syncthreads();
#pragma unroll
            for (int f4 = 0; f4 < 3; f4++) {     // 24x128 contiguous floats
                int f = tid + 256 * f4;
                *(float4*)&As[f >> 5][(f & 31) << 2] =
                    *(const float4*)(kerb + (cpass * 8 + it) * 3072 + (f << 2));
            }
            __syncthreads();
#pragma unroll
            for (int di = 0; di < 8; di++) {
                const float* hrow = &hs[it * 8 + di][s0];
                float w[10];
#pragma unroll
                for (int j = 0; j < 10; j++) w[j] = hrow[j];
#pragma unroll
                for (int k = 0; k < 3; k++) {
                    const float4 a0 = *(const float4*)&As[di * 3 + k][o0];
                    const float4 a1 = *(const float4*)&As[di * 3 + k][o0 + 4];
                    const float av[8] = {a0.x, a0.y, a0.z, a0.w, a1.x, a1.y, a1.z, a1.w};
#pragma unroll
                    for (int oi = 0; oi < 8; oi++)
#pragma unroll
                        for (int si = 0; si < 8; si++)
                            acc[oi][si] += av[oi] * w[k + si];
                }
            }
        }
    }

    const float* bb = g_ballT + ((long)(b * LC + l)) * 512 + layer * HID;
#pragma unroll
    for (int oi = 0; oi < 8; oi++) {
        const float bv = bb[o0 + oi];
        float* dst = g_hB + hb + (long)(o0 + oi) * T_LEN + t0 + s0;
        float4 v0, v1;
        {float u=acc[oi][0]+bv; v0.x=u>=0.f?u:3.f*u;} {float u=acc[oi][1]+bv; v0.y=u>=0.f?u:3.f*u;}
        {float u=acc[oi][2]+bv; v0.z=u>=0.f?u:3.f*u;} {float u=acc[oi][3]+bv; v0.w=u>=0.f?u:3.f*u;}
        {float u=acc[oi][4]+bv; v1.x=u>=0.f?u:3.f*u;} {float u=acc[oi][5]+bv; v1.y=u>=0.f?u:3.f*u;}
        {float u=acc[oi][6]+bv; v1.z=u>=0.f?u:3.f*u;} {float u=acc[oi][7]+bv; v1.w=u>=0.f?u:3.f*u;}
        *(float4*)dst = v0; *(float4*)(dst + 4) = v1;
    }
}

// ---------------- dilated conv layer: g_hB -> g_hA ----------------
// out[b,o,t] = leaky( sum_{i,k} hB[b,i,t+(k-1)*d]*w[layer,o,i,k] + block_b[layer,o], 3 )
// Static smem only: 32-channel input slab, 4 passes. Row pitch 184 covers d<=27.
__global__ void __launch_bounds__(256, 2) k_dil(const float* __restrict__ bbias,
                                                int layer, int d) {
    __shared__ __align__(16) float hs[32][184]; // 23.6 KB
    __shared__ __align__(16) float As[24][128]; // 12.3 KB

    const int tb = blockIdx.x, b = blockIdx.y;
    const int t0 = tb * 128;
    const int W = 128 + 2 * d;                  // valid cols: 0..W-1 = t0-d .. t0+127+d
    const int tid = threadIdx.x, wid = tid >> 5, lane = tid & 31;
    const long hb = (long)b * HID * T_LEN;

    const float* wb = g_wT + (long)layer * LAYER_R;
    float acc[8][8];
#pragma unroll
    for (int i = 0; i < 8; i++)
#pragma unroll
        for (int j = 0; j < 8; j++) acc[i][j] = 0.f;

    const int ri = tid & 15, li = tid >> 4;
    const int o0 = ri * 8, s0 = li * 8;

    for (int cpass = 0; cpass < 4; cpass++) {
        __syncthreads();
        const int c0 = cpass * 32;
        for (int i = wid; i < 32; i += 8) {
            const float* src = g_hB + hb + (long)(c0 + i) * T_LEN;
            for (int tt = lane; tt < W; tt += 32) {
                int t = t0 - d + tt;
                hs[i][tt] = (t >= 0 && t < T_LEN) ? src[t] : 0.f;
            }
        }
        for (int it = 0; it < 4; it++) {
            __syncthreads();
#pragma unroll
            for (int f4 = 0; f4 < 3; f4++) {
                int f = tid + 256 * f4;
                *(float4*)&As[f >> 5][(f & 31) << 2] =
                    *(const float4*)(wb + (cpass * 4 + it) * 3072 + (f << 2));
            }
            __syncthreads();
#pragma unroll
            for (int di = 0; di < 8; di++) {
                const float* hrow = &hs[it * 8 + di][s0];
#pragma unroll
                for (int k = 0; k < 3; k++) {
                    float w[8];
#pragma unroll
                    for (int j = 0; j < 8; j++) w[j] = hrow[k * d + j];
                    const float4 a0 = *(const float4*)&As[di * 3 + k][o0];
                    const float4 a1 = *(const float4*)&As[di * 3 + k][o0 + 4];
                    const float av[8] = {a0.x, a0.y, a0.z, a0.w, a1.x, a1.y, a1.z, a1.w};
#pragma unroll
                    for (int oi = 0; oi < 8; oi++)
#pragma unroll
                        for (int si = 0; si < 8; si++)
                            acc[oi][si] += av[oi] * w[si];
                }
            }
        }
    }

#pragma unroll
    for (int oi = 0; oi < 8; oi++) {
        const float bv = bbias[layer * HID + o0 + oi];
        float* dst = g_hA + hb + (long)(o0 + oi) * T_LEN + t0 + s0;
        float4 v0, v1;
        {float u=acc[oi][0]+bv; v0.x=u>=0.f?u:3.f*u;} {float u=acc[oi][1]+bv; v0.y=u>=0.f?u:3.f*u;}
        {float u=acc[oi][2]+bv; v0.z=u>=0.f?u:3.f*u;} {float u=acc[oi][3]+bv; v0.w=u>=0.f?u:3.f*u;}
        {float u=acc[oi][4]+bv; v1.x=u>=0.f?u:3.f*u;} {float u=acc[oi][5]+bv; v1.y=u>=0.f?u:3.f*u;}
        {float u=acc[oi][6]+bv; v1.z=u>=0.f?u:3.f*u;} {float u=acc[oi][7]+bv; v1.w=u>=0.f?u:3.f*u;}
        *(float4*)dst = v0; *(float4*)(dst + 4) = v1;
    }
}

// ---------------- postconv ----------------
__global__ void k_post(const float* __restrict__ pw, const float* __restrict__ pb,
                       float* __restrict__ out) {
    __shared__ float wsh[128];
    const int b = blockIdx.y;
    const int t = blockIdx.x * 256 + threadIdx.x;
    if (threadIdx.x < 128) wsh[threadIdx.x] = pw[threadIdx.x];
    __syncthreads();
    const float* hp = g_hA + (long)b * HID * T_LEN + t;
    float acc = pb[0];
#pragma unroll 8
    for (int ch = 0; ch < 128; ch++) acc += wsh[ch] * hp[(long)ch * T_LEN];
    out[(long)b * T_LEN + t] = acc;
}

// ---------------- launch ----------------
extern "C" void kernel_launch(void* const* d_in, const int* in_sizes, int n_in,
                              void* d_out, int out_size) {
    const float* x        = (const float*)d_in[0];
    const float* c        = (const float*)d_in[1];
    const float* kernel_w = (const float*)d_in[2];
    const float* kernel_b = (const float*)d_in[3];
    const float* biasp_w  = (const float*)d_in[4];
    const float* biasp_b  = (const float*)d_in[5];
    const float* pre_w    = (const float*)d_in[6];
    const float* pre_b    = (const float*)d_in[7];
    const float* block_w  = (const float*)d_in[8];
    const float* block_b  = (const float*)d_in[9];
    const float* post_w   = (const float*)d_in[10];
    const float* post_b   = (const float*)d_in[11];
    float* out = (float*)d_out;

    k_permw<<<768, 256>>>(block_w);
    k_pre<<<dim3(128, 512), 256>>>(x, pre_w, pre_b);
    k_biasp<<<dim3(512, 4), 128>>>(biasp_w, biasp_b, c);

    const int dils[4] = {1, 3, 9, 27};
    for (int layer = 0; layer < 4; layer++) {
        k_gemm_pred<<<dim3(4, 384), 256>>>(kernel_w, kernel_b, c, layer);
        k_lvc<<<dim3(2, 128, 4), 256>>>(layer);
        k_dil<<<dim3(256, 4), 256>>>(block_b, layer, dils[layer]);
    }
    k_post<<<dim3(128, 4), 256>>>(post_w, post_b, out);
}

// round 7
// speedup vs baseline: 1.0467x; 1.0467x over previous
#include <cuda_runtime.h>
#include <cstdint>

#define T_LEN   32768
#define B_SZ    4
#define HID     128
#define NL      4
#define KERS    3
#define CONDC   512
#define LC      128
#define HOPSZ   256
#define LAYER_R 49152   /* HID*HID*KERS */

// packed f32x2 helpers (Blackwell): bit-identical IEEE fp32 FMA on both lanes
#define FMA2(acc, a, b) asm("fma.rn.f32x2 %0, %1, %2, %0;" : "+l"(acc) : "l"(a), "l"(b))
#define DUP2(d, f)      asm("mov.b64 %0, {%1, %1};" : "=l"(d) : "f"(f))
#define UNPK2(lo, hi, v) asm("mov.b64 {%0, %1}, %2;" : "=f"(lo), "=f"(hi) : "l"(v))

// ---------------- scratch (device globals; no allocation) ----------------
static __device__ float g_kallp[(size_t)B_SZ * LC * LAYER_R]; // 100.7 MB, per-layer reuse
static __device__ float g_hA[(size_t)B_SZ * HID * T_LEN];     // 64 MB
static __device__ float g_hB[(size_t)B_SZ * HID * T_LEN];     // 64 MB
static __device__ float g_ballT[B_SZ * LC * 512];             // 1 MB  [b][l][layer*128+o]
static __device__ float g_wT[NL * HID * KERS * HID];          // 0.75 MB [layer][i][k][o]

// ---------------- tiny setup: permute dilated-conv weights ----------------
__global__ void k_permw(const float* __restrict__ bw) {
    int s = blockIdx.x * 256 + threadIdx.x;
    if (s >= NL * HID * HID * KERS) return;
    int k = s % 3; int q = s / 3;
    int i = q % 128; q /= 128;
    int o = q % 128; int layer = q / 128;
    g_wT[((layer * 128 + i) * 3 + k) * 128 + o] = bw[s];
}

// ---------------- preconv ----------------
__global__ void k_pre(const float* __restrict__ x, const float* __restrict__ pw,
                      const float* __restrict__ pb) {
    const int bc = blockIdx.y;
    const int t  = blockIdx.x * 256 + threadIdx.x;
    const int b  = bc >> 7, ch = bc & 127;
    float v = pw[ch] * x[(long)b * T_LEN + t] + pb[ch];
    v = v >= 0.f ? v : 0.2f * v;
    g_hA[(long)bc * T_LEN + t] = v;
}

// ---------------- bias predictor ----------------
__global__ void k_biasp(const float* __restrict__ bw, const float* __restrict__ bb,
                        const float* __restrict__ cc) {
    const int row = blockIdx.x, b = blockIdx.y;
    const int l = threadIdx.x;
    const float* cp = cc + (long)b * CONDC * LC + l;
    const float* wp = bw + (long)row * CONDC;
    float acc = bb[row];
#pragma unroll 8
    for (int c2 = 0; c2 < CONDC; c2++) acc += wp[c2] * cp[(long)c2 * LC];
    g_ballT[((long)(b * LC + l)) * 512 + row] = acc;
}

// ---------------- kernel-predictor GEMM (one layer), f32x2 packed ----------------
// acc pairs packed along r (rows of As are contiguous -> free ulonglong2 loads)
__global__ void __launch_bounds__(256, 2)
k_gemm_pred(const float* __restrict__ kw, const float* __restrict__ kb,
            const float* __restrict__ cc, int layer) {
    const int b = blockIdx.x;
    const int m = blockIdx.y;                   // 0..383
    const int ic  = m / 3;
    const int kof = m - ic * 3;
    const long rowbase = ((long)(layer * HID + ic) * HID) * KERS + kof;

    __shared__ __align__(16) float As[16][132]; // [k][r]
    __shared__ __align__(16) float Bs[16][128]; // [k][l]

    const int tid = threadIdx.x;
    const int ri = tid & 15, li = tid >> 4;
    const int r0 = ri * 8, l0 = li * 8;

    unsigned long long acc2[4][8];              // [r-pair][l]
#pragma unroll
    for (int i = 0; i < 4; i++)
#pragma unroll
        for (int j = 0; j < 8; j++) acc2[i][j] = 0ULL;

    const float* cb = cc + (long)b * CONDC * LC;

    for (int kt = 0; kt < CONDC; kt += 16) {
        __syncthreads();
#pragma unroll
        for (int it = 0; it < 2; it++) {        // A tile: 128 rows x 16 k
            int f = tid + 256 * it;
            int rr = f >> 2, kq = f & 3;
            float4 v = *(const float4*)(kw + (rowbase + 3L * rr) * CONDC + kt + (kq << 2));
            As[(kq << 2) + 0][rr] = v.x; As[(kq << 2) + 1][rr] = v.y;
            As[(kq << 2) + 2][rr] = v.z; As[(kq << 2) + 3][rr] = v.w;
        }
#pragma unroll
        for (int it = 0; it < 2; it++) {        // B tile: 16 k x 128 l
            int f = tid + 256 * it;
            int kr = f >> 5, lq = f & 31;
            *(float4*)&Bs[kr][lq << 2] = *(const float4*)(cb + (long)(kt + kr) * LC + (lq << 2));
        }
        __syncthreads();
#pragma unroll
        for (int ks = 0; ks < 16; ks++) {
            const ulonglong2 a01 = *(const ulonglong2*)&As[ks][r0];
            const ulonglong2 a23 = *(const ulonglong2*)&As[ks][r0 + 4];
            const float4 c0 = *(const float4*)&Bs[ks][l0];
            const float4 c1 = *(const float4*)&Bs[ks][l0 + 4];
            const float bvv[8] = {c0.x, c0.y, c0.z, c0.w, c1.x, c1.y, c1.z, c1.w};
#pragma unroll
            for (int j = 0; j < 8; j++) {
                unsigned long long bd; DUP2(bd, bvv[j]);
                FMA2(acc2[0][j], a01.x, bd);
                FMA2(acc2[1][j], a01.y, bd);
                FMA2(acc2[2][j], a23.x, bd);
                FMA2(acc2[3][j], a23.y, bd);
            }
        }
    }

    float bias[8];
#pragma unroll
    for (int i = 0; i < 8; i++) bias[i] = kb[rowbase + 3 * (r0 + i)];

#pragma unroll
    for (int lj = 0; lj < 8; lj++) {
        float r[8];
#pragma unroll
        for (int i2 = 0; i2 < 4; i2++) UNPK2(r[2 * i2], r[2 * i2 + 1], acc2[i2][lj]);
        float* dst = g_kallp + ((long)(b * LC + l0 + lj)) * LAYER_R + m * 128 + r0;
        float4 v0, v1;
        v0.x = r[0] + bias[0]; v0.y = r[1] + bias[1];
        v0.z = r[2] + bias[2]; v0.w = r[3] + bias[3];
        v1.x = r[4] + bias[4]; v1.y = r[5] + bias[5];
        v1.z = r[6] + bias[6]; v1.w = r[7] + bias[7];
        *(float4*)dst = v0; *(float4*)(dst + 4) = v1;
    }
}

// ---------------- LVC layer: g_hA -> g_hB, f32x2 packed along o ----------------
__global__ void __launch_bounds__(256, 2) k_lvc(int layer) {
    __shared__ __align__(16) float hs[64][132]; // 33.8 KB
    __shared__ __align__(16) float As[24][128]; // 12.3 KB; [(i%8)*3+k][o]

    const int sh = blockIdx.x, l = blockIdx.y, b = blockIdx.z;
    const int t0 = l * HOPSZ + sh * 128;
    const int tid = threadIdx.x;
    const int wid = tid >> 5, lane = tid & 31;
    const long hb = (long)b * HID * T_LEN;

    const float* kerb = g_kallp + ((long)(b * LC + l)) * LAYER_R;
    unsigned long long acc2[4][8];              // [o-pair][s]
#pragma unroll
    for (int i = 0; i < 4; i++)
#pragma unroll
        for (int j = 0; j < 8; j++) acc2[i][j] = 0ULL;

    const int ri = tid & 15, li = tid >> 4;
    const int o0 = ri * 8, s0 = li * 8;

    for (int cpass = 0; cpass < 2; cpass++) {
        __syncthreads();
        const int c0 = cpass * 64;
        for (int i = wid; i < 64; i += 8) {
            const float* src = g_hA + hb + (long)(c0 + i) * T_LEN;
            for (int tt = lane; tt < 130; tt += 32) {
                int t = t0 - 1 + tt;
                hs[i][tt] = (t >= 0 && t < T_LEN) ? src[t] : 0.f;
            }
        }
        for (int it = 0; it < 8; it++) {
            __syncthreads();
#pragma unroll
            for (int f4 = 0; f4 < 3; f4++) {
                int f = tid + 256 * f4;
                *(float4*)&As[f >> 5][(f & 31) << 2] =
                    *(const float4*)(kerb + (cpass * 8 + it) * 3072 + (f << 2));
            }
            __syncthreads();
#pragma unroll
            for (int di = 0; di < 8; di++) {
                const float* hrow = &hs[it * 8 + di][s0];
                unsigned long long wd[10];
#pragma unroll
                for (int j = 0; j < 10; j++) { float t = hrow[j]; DUP2(wd[j], t); }
#pragma unroll
                for (int k = 0; k < 3; k++) {
                    const ulonglong2 a01 = *(const ulonglong2*)&As[di * 3 + k][o0];
                    const ulonglong2 a23 = *(const ulonglong2*)&As[di * 3 + k][o0 + 4];
#pragma unroll
                    for (int si = 0; si < 8; si++) {
                        FMA2(acc2[0][si], a01.x, wd[k + si]);
                        FMA2(acc2[1][si], a01.y, wd[k + si]);
                        FMA2(acc2[2][si], a23.x, wd[k + si]);
                        FMA2(acc2[3][si], a23.y, wd[k + si]);
                    }
                }
            }
        }
    }

    const float* bb = g_ballT + ((long)(b * LC + l)) * 512 + layer * HID;
#pragma unroll
    for (int oi2 = 0; oi2 < 4; oi2++) {
        float rlo[8], rhi[8];
#pragma unroll
        for (int si = 0; si < 8; si++) UNPK2(rlo[si], rhi[si], acc2[oi2][si]);
        const int oa = o0 + 2 * oi2, ob = oa + 1;
        const float bva = bb[oa], bvb = bb[ob];
        float* da = g_hB + hb + (long)oa * T_LEN + t0 + s0;
        float* db2 = g_hB + hb + (long)ob * T_LEN + t0 + s0;
        float4 v0, v1;
        {float u=rlo[0]+bva; v0.x=u>=0.f?u:3.f*u;} {float u=rlo[1]+bva; v0.y=u>=0.f?u:3.f*u;}
        {float u=rlo[2]+bva; v0.z=u>=0.f?u:3.f*u;} {float u=rlo[3]+bva; v0.w=u>=0.f?u:3.f*u;}
        {float u=rlo[4]+bva; v1.x=u>=0.f?u:3.f*u;} {float u=rlo[5]+bva; v1.y=u>=0.f?u:3.f*u;}
        {float u=rlo[6]+bva; v1.z=u>=0.f?u:3.f*u;} {float u=rlo[7]+bva; v1.w=u>=0.f?u:3.f*u;}
        *(float4*)da = v0; *(float4*)(da + 4) = v1;
        {float u=rhi[0]+bvb; v0.x=u>=0.f?u:3.f*u;} {float u=rhi[1]+bvb; v0.y=u>=0.f?u:3.f*u;}
        {float u=rhi[2]+bvb; v0.z=u>=0.f?u:3.f*u;} {float u=rhi[3]+bvb; v0.w=u>=0.f?u:3.f*u;}
        {float u=rhi[4]+bvb; v1.x=u>=0.f?u:3.f*u;} {float u=rhi[5]+bvb; v1.y=u>=0.f?u:3.f*u;}
        {float u=rhi[6]+bvb; v1.z=u>=0.f?u:3.f*u;} {float u=rhi[7]+bvb; v1.w=u>=0.f?u:3.f*u;}
        *(float4*)db2 = v0; *(float4*)(db2 + 4) = v1;
    }
}

// ---------------- dilated conv layer: g_hB -> g_hA, f32x2 packed along o ----------------
__global__ void __launch_bounds__(256, 2) k_dil(const float* __restrict__ bbias,
                                                int layer, int d) {
    __shared__ __align__(16) float hs[32][184]; // 23.6 KB
    __shared__ __align__(16) float As[24][128]; // 12.3 KB

    const int tb = blockIdx.x, b = blockIdx.y;
    const int t0 = tb * 128;
    const int W = 128 + 2 * d;
    const int tid = threadIdx.x, wid = tid >> 5, lane = tid & 31;
    const long hb = (long)b * HID * T_LEN;

    const float* wb = g_wT + (long)layer * LAYER_R;
    unsigned long long acc2[4][8];
#pragma unroll
    for (int i = 0; i < 4; i++)
#pragma unroll
        for (int j = 0; j < 8; j++) acc2[i][j] = 0ULL;

    const int ri = tid & 15, li = tid >> 4;
    const int o0 = ri * 8, s0 = li * 8;

    for (int cpass = 0; cpass < 4; cpass++) {
        __syncthreads();
        const int c0 = cpass * 32;
        for (int i = wid; i < 32; i += 8) {
            const float* src = g_hB + hb + (long)(c0 + i) * T_LEN;
            for (int tt = lane; tt < W; tt += 32) {
                int t = t0 - d + tt;
                hs[i][tt] = (t >= 0 && t < T_LEN) ? src[t] : 0.f;
            }
        }
        for (int it = 0; it < 4; it++) {
            __syncthreads();
#pragma unroll
            for (int f4 = 0; f4 < 3; f4++) {
                int f = tid + 256 * f4;
                *(float4*)&As[f >> 5][(f & 31) << 2] =
                    *(const float4*)(wb + (cpass * 4 + it) * 3072 + (f << 2));
            }
            __syncthreads();
#pragma unroll
            for (int di = 0; di < 8; di++) {
                const float* hrow = &hs[it * 8 + di][s0];
#pragma unroll
                for (int k = 0; k < 3; k++) {
                    unsigned long long wd[8];
#pragma unroll
                    for (int j = 0; j < 8; j++) { float t = hrow[k * d + j]; DUP2(wd[j], t); }
                    const ulonglong2 a01 = *(const ulonglong2*)&As[di * 3 + k][o0];
                    const ulonglong2 a23 = *(const ulonglong2*)&As[di * 3 + k][o0 + 4];
#pragma unroll
                    for (int si = 0; si < 8; si++) {
                        FMA2(acc2[0][si], a01.x, wd[si]);
                        FMA2(acc2[1][si], a01.y, wd[si]);
                        FMA2(acc2[2][si], a23.x, wd[si]);
                        FMA2(acc2[3][si], a23.y, wd[si]);
                    }
                }
            }
        }
    }

#pragma unroll
    for (int oi2 = 0; oi2 < 4; oi2++) {
        float rlo[8], rhi[8];
#pragma unroll
        for (int si = 0; si < 8; si++) UNPK2(rlo[si], rhi[si], acc2[oi2][si]);
        const int oa = o0 + 2 * oi2, ob = oa + 1;
        const float bva = bbias[layer * HID + oa], bvb = bbias[layer * HID + ob];
        float* da = g_hA + hb + (long)oa * T_LEN + t0 + s0;
        float* db2 = g_hA + hb + (long)ob * T_LEN + t0 + s0;
        float4 v0, v1;
        {float u=rlo[0]+bva; v0.x=u>=0.f?u:3.f*u;} {float u=rlo[1]+bva; v0.y=u>=0.f?u:3.f*u;}
        {float u=rlo[2]+bva; v0.z=u>=0.f?u:3.f*u;} {float u=rlo[3]+bva; v0.w=u>=0.f?u:3.f*u;}
        {float u=rlo[4]+bva; v1.x=u>=0.f?u:3.f*u;} {float u=rlo[5]+bva; v1.y=u>=0.f?u:3.f*u;}
        {float u=rlo[6]+bva; v1.z=u>=0.f?u:3.f*u;} {float u=rlo[7]+bva; v1.w=u>=0.f?u:3.f*u;}
        *(float4*)da = v0; *(float4*)(da + 4) = v1;
        {float u=rhi[0]+bvb; v0.x=u>=0.f?u:3.f*u;} {float u=rhi[1]+bvb; v0.y=u>=0.f?u:3.f*u;}
        {float u=rhi[2]+bvb; v0.z=u>=0.f?u:3.f*u;} {float u=rhi[3]+bvb; v0.w=u>=0.f?u:3.f*u;}
        {float u=rhi[4]+bvb; v1.x=u>=0.f?u:3.f*u;} {float u=rhi[5]+bvb; v1.y=u>=0.f?u:3.f*u;}
        {float u=rhi[6]+bvb; v1.z=u>=0.f?u:3.f*u;} {float u=rhi[7]+bvb; v1.w=u>=0.f?u:3.f*u;}
        *(float4*)db2 = v0; *(float4*)(db2 + 4) = v1;
    }
}

// ---------------- postconv ----------------
__global__ void k_post(const float* __restrict__ pw, const float* __restrict__ pb,
                       float* __restrict__ out) {
    __shared__ float wsh[128];
    const int b = blockIdx.y;
    const int t = blockIdx.x * 256 + threadIdx.x;
    if (threadIdx.x < 128) wsh[threadIdx.x] = pw[threadIdx.x];
    __syncthreads();
    const float* hp = g_hA + (long)b * HID * T_LEN + t;
    float acc = pb[0];
#pragma unroll 8
    for (int ch = 0; ch < 128; ch++) acc += wsh[ch] * hp[(long)ch * T_LEN];
    out[(long)b * T_LEN + t] = acc;
}

// ---------------- launch ----------------
extern "C" void kernel_launch(void* const* d_in, const int* in_sizes, int n_in,
                              void* d_out, int out_size) {
    const float* x        = (const float*)d_in[0];
    const float* c        = (const float*)d_in[1];
    const float* kernel_w = (const float*)d_in[2];
    const float* kernel_b = (const float*)d_in[3];
    const float* biasp_w  = (const float*)d_in[4];
    const float* biasp_b  = (const float*)d_in[5];
    const float* pre_w    = (const float*)d_in[6];
    const float* pre_b    = (const float*)d_in[7];
    const float* block_w  = (const float*)d_in[8];
    const float* block_b  = (const float*)d_in[9];
    const float* post_w   = (const float*)d_in[10];
    const float* post_b   = (const float*)d_in[11];
    float* out = (float*)d_out;

    k_permw<<<768, 256>>>(block_w);
    k_pre<<<dim3(128, 512), 256>>>(x, pre_w, pre_b);
    k_biasp<<<dim3(512, 4), 128>>>(biasp_w, biasp_b, c);

    const int dils[4] = {1, 3, 9, 27};
    for (int layer = 0; layer < 4; layer++) {
        k_gemm_pred<<<dim3(4, 384), 256>>>(kernel_w, kernel_b, c, layer);
        k_lvc<<<dim3(2, 128, 4), 256>>>(layer);
        k_dil<<<dim3(256, 4), 256>>>(block_b, layer, dils[layer]);
    }
    k_post<<<dim3(128, 4), 256>>>(post_w, post_b, out);
}

// round 9
// speedup vs baseline: 1.3543x; 1.2938x over previous
#include <cuda_runtime.h>
#include <cuda_bf16.h>
#include <cstdint>

#define T_LEN   32768
#define B_SZ    4
#define HID     128
#define NL      4
#define KERS    3
#define CONDC   512
#define LC      128
#define HOPSZ   256
#define LAYER_R 49152   /* HID*HID*KERS */
#define NM      384     /* m-tiles per layer: HID*KERS */

// packed f32x2 helpers (Blackwell)
#define FMA2(acc, a, b) asm("fma.rn.f32x2 %0, %1, %2, %0;" : "+l"(acc) : "l"(a), "l"(b))
#define DUP2(d, f)      asm("mov.b64 %0, {%1, %1};" : "=l"(d) : "f"(f))
#define UNPK2(lo, hi, v) asm("mov.b64 {%0, %1}, %2;" : "=f"(lo), "=f"(hi) : "l"(v))

// ---------------- scratch (device globals; no allocation) ----------------
static __device__ float g_kallp[(size_t)B_SZ * LC * LAYER_R]; // 100.7 MB, per-layer reuse
static __device__ float g_hA[(size_t)B_SZ * HID * T_LEN];     // 64 MB
static __device__ float g_hB[(size_t)B_SZ * HID * T_LEN];     // 64 MB
static __device__ float g_ballT[B_SZ * LC * 512];             // 1 MB
static __device__ float g_wT[NL * HID * KERS * HID];          // 0.75 MB [layer][i][k][o]
// bf16 hi/lo split of kernel_w, pre-permuted: [layer][m][rr][c]
static __device__ __nv_bfloat16 g_kwhi[(size_t)NL * NM * HID * CONDC];
static __device__ __nv_bfloat16 g_kwlo[(size_t)NL * NM * HID * CONDC];
// bf16 hi/lo split of c, transposed: [b][l][cond]
static __device__ __nv_bfloat16 g_chi[B_SZ * LC * CONDC];
static __device__ __nv_bfloat16 g_clo[B_SZ * LC * CONDC];

__device__ __forceinline__ uint32_t smem_u32(const void* p) {
    uint32_t a;
    asm("{ .reg .u64 t; cvta.to.shared.u64 t, %1; cvt.u32.u64 %0, t; }" : "=r"(a) : "l"(p));
    return a;
}
__device__ __forceinline__ void ldmx4(uint32_t* r, uint32_t addr) {
    asm volatile("ldmatrix.sync.aligned.m8n8.x4.shared.b16 {%0,%1,%2,%3}, [%4];"
                 : "=r"(r[0]), "=r"(r[1]), "=r"(r[2]), "=r"(r[3]) : "r"(addr));
}
__device__ __forceinline__ void mma_bf16(float* c, const uint32_t* a, uint32_t b0, uint32_t b1) {
    asm volatile(
        "mma.sync.aligned.m16n8k16.row.col.f32.bf16.bf16.f32 "
        "{%0,%1,%2,%3}, {%4,%5,%6,%7}, {%8,%9}, {%0,%1,%2,%3};"
        : "+f"(c[0]), "+f"(c[1]), "+f"(c[2]), "+f"(c[3])
        : "r"(a[0]), "r"(a[1]), "r"(a[2]), "r"(a[3]), "r"(b0), "r"(b1));
}

// ---------------- setup kernels ----------------
__global__ void k_permw(const float* __restrict__ bw) {
    int s = blockIdx.x * 256 + threadIdx.x;
    if (s >= NL * HID * HID * KERS) return;
    int k = s % 3; int q = s / 3;
    int i = q % 128; q /= 128;
    int o = q % 128; int layer = q / 128;
    g_wT[((layer * 128 + i) * 3 + k) * 128 + o] = bw[s];
}

// kernel_w fp32 -> permuted bf16 hi/lo.  4 elems/thread.
__global__ void k_cvt_kw(const float* __restrict__ kw) {
    long g = (long)blockIdx.x * 256 + threadIdx.x;
    int c4 = (int)(g & 127);
    long rowp = g >> 7;                              // permuted row 0..786431
    int rr = (int)(rowp & 127);
    int mm = (int)(rowp >> 7);
    int m = mm % NM, layer = mm / NM;
    int ic = m / 3, kof = m - ic * 3;
    long srow = ((long)(layer * 128 + ic) * 128) * 3 + kof + 3L * rr;
    float4 v = *(const float4*)(kw + srow * CONDC + c4 * 4);
    __nv_bfloat16 h0 = __float2bfloat16(v.x), h1 = __float2bfloat16(v.y);
    __nv_bfloat16 h2 = __float2bfloat16(v.z), h3 = __float2bfloat16(v.w);
    __nv_bfloat16 l0 = __float2bfloat16(v.x - __bfloat162float(h0));
    __nv_bfloat16 l1 = __float2bfloat16(v.y - __bfloat162float(h1));
    __nv_bfloat16 l2 = __float2bfloat16(v.z - __bfloat162float(h2));
    __nv_bfloat16 l3 = __float2bfloat16(v.w - __bfloat162float(h3));
    ushort4 uh = make_ushort4(__bfloat16_as_ushort(h0), __bfloat16_as_ushort(h1),
                              __bfloat16_as_ushort(h2), __bfloat16_as_ushort(h3));
    ushort4 ul = make_ushort4(__bfloat16_as_ushort(l0), __bfloat16_as_ushort(l1),
                              __bfloat16_as_ushort(l2), __bfloat16_as_ushort(l3));
    *(ushort4*)(g_kwhi + rowp * CONDC + c4 * 4) = uh;
    *(ushort4*)(g_kwlo + rowp * CONDC + c4 * 4) = ul;
}

// c fp32 [b][cond][l] -> bf16 hi/lo [b][l][cond]
__global__ void k_cvt_c(const float* __restrict__ cc) {
    int g = blockIdx.x * 256 + threadIdx.x;          // 262144
    int l = g & 127, q = g >> 7;
    int cond = q & 511, b = q >> 9;
    float v = cc[((long)b * CONDC + cond) * LC + l];
    __nv_bfloat16 h = __float2bfloat16(v);
    __nv_bfloat16 lo = __float2bfloat16(v - __bfloat162float(h));
    g_chi[((long)b * LC + l) * CONDC + cond] = h;
    g_clo[((long)b * LC + l) * CONDC + cond] = lo;
}

// ---------------- preconv ----------------
__global__ void k_pre(const float* __restrict__ x, const float* __restrict__ pw,
                      const float* __restrict__ pb) {
    const int bc = blockIdx.y;
    const int t  = blockIdx.x * 256 + threadIdx.x;
    const int b  = bc >> 7, ch = bc & 127;
    float v = pw[ch] * x[(long)b * T_LEN + t] + pb[ch];
    v = v >= 0.f ? v : 0.2f * v;
    g_hA[(long)bc * T_LEN + t] = v;
}

// ---------------- bias predictor ----------------
__global__ void k_biasp(const float* __restrict__ bw, const float* __restrict__ bb,
                        const float* __restrict__ cc) {
    const int row = blockIdx.x, b = blockIdx.y;
    const int l = threadIdx.x;
    const float* cp = cc + (long)b * CONDC * LC + l;
    const float* wp = bw + (long)row * CONDC;
    float acc = bb[row];
#pragma unroll 8
    for (int c2 = 0; c2 < CONDC; c2++) acc += wp[c2] * cp[(long)c2 * LC];
    g_ballT[((long)(b * LC + l)) * 512 + row] = acc;
}

// ---------------- kernel-predictor GEMM via mma.sync bf16 (one layer) ----------------
// D[l][rr] = sum_c c[b][l][c] * kw_perm[layer][m][rr][c] + bias.
// A rows = l (g_chi/g_clo), B rows = rr (g_kwhi/g_kwlo), both K-contiguous -> row.col.
// 3 split terms: hi*hi + hi*lo + lo*hi, fp32 register accumulators.
__global__ void __launch_bounds__(256, 2)
k_mma_pred(const float* __restrict__ kb, int layer) {
    __shared__ __align__(1024) __nv_bfloat16 sA[128 * 64]; // 16 KB, SW128 swizzled
    __shared__ __align__(1024) __nv_bfloat16 sB[128 * 64]; // 16 KB
    __shared__ float sbias[128];

    const int b = blockIdx.x, m = blockIdx.y;
    const int tid = threadIdx.x, lane = tid & 31, wid = tid >> 5;
    const int warp_m = wid >> 1, warp_n = wid & 1;   // 4 x 2 warp grid
    const int ic = m / 3, kof = m - ic * 3;
    const long rowbase = ((long)(layer * HID + ic) * HID) * KERS + kof;

    if (tid < 128) sbias[tid] = kb[rowbase + 3L * tid];

    const __nv_bfloat16* aHi = g_chi + (size_t)b * 128 * CONDC;
    const __nv_bfloat16* aLo = g_clo + (size_t)b * 128 * CONDC;
    const __nv_bfloat16* bHi = g_kwhi + (size_t)(layer * NM + m) * 128 * CONDC;
    const __nv_bfloat16* bLo = g_kwlo + (size_t)(layer * NM + m) * 128 * CONDC;

    float acc[2][8][4];
#pragma unroll
    for (int i = 0; i < 2; i++)
#pragma unroll
        for (int j = 0; j < 8; j++)
#pragma unroll
            for (int k = 0; k < 4; k++) acc[i][j][k] = 0.f;

    const uint32_t sAu = smem_u32(sA), sBu = smem_u32(sB);
    // ldmatrix lane address precompute.
    // A x4 tiles: t0(r0-7,kLo) t1(r8-15,kLo) t2(r0-7,kHi) t3(r8-15,kHi)
    const int at = lane >> 3;
    const int a_row = warp_m * 32 + (at & 1) * 8 + (lane & 7);   // + mb*16
    const int a_kb  = (at >> 1) * 16;                            // + s*32
    // B x4 tiles: t0(n0-7,kLo) t1(n0-7,kHi) t2(n8-15,kLo) t3(n8-15,kHi)
    const int b_row = warp_n * 64 + (at >> 1) * 8 + (lane & 7);  // + j2*16
    const int b_kb  = (at & 1) * 16;

    for (int term = 0; term < 3; term++) {
        const __nv_bfloat16* srcA = (term == 2) ? aLo : aHi;
        const __nv_bfloat16* srcB = (term == 1) ? bLo : bHi;
#pragma unroll 1
        for (int chunk = 0; chunk < 8; chunk++) {
            const int c0 = chunk * 64;
            __syncthreads();                          // prior reads done
            for (int q = tid; q < 2048; q += 256) {   // stage A,B 128x64 tiles
                int tile = q >> 10, qq = q & 1023;
                int rr = qq >> 3, c8 = qq & 7;
                uint32_t off = rr * 128 + c8 * 16;
                uint32_t sw = off ^ ((off >> 3) & 0x70);
                const __nv_bfloat16* src = (tile ? srcB : srcA) + (size_t)rr * CONDC + c0 + c8 * 8;
                *(uint4*)((char*)(tile ? sB : sA) + sw) = *(const uint4*)src;
            }
            __syncthreads();
#pragma unroll
            for (int s = 0; s < 4; s++) {
                uint32_t aF[2][4];
#pragma unroll
                for (int mb = 0; mb < 2; mb++) {
                    int row = a_row + mb * 16;
                    int kbyte = (a_kb + s * 32) ^ ((row & 7) << 4);
                    ldmx4(aF[mb], sAu + row * 128 + kbyte);
                }
                uint32_t bF[4][4];
#pragma unroll
                for (int j2 = 0; j2 < 4; j2++) {
                    int row = b_row + j2 * 16;
                    int kbyte = (b_kb + s * 32) ^ ((row & 7) << 4);
                    ldmx4(bF[j2], sBu + row * 128 + kbyte);
                }
#pragma unroll
                for (int mb = 0; mb < 2; mb++)
#pragma unroll
                    for (int j2 = 0; j2 < 4; j2++) {
                        mma_bf16(acc[mb][2 * j2],     aF[mb], bF[j2][0], bF[j2][1]);
                        mma_bf16(acc[mb][2 * j2 + 1], aF[mb], bF[j2][2], bF[j2][3]);
                    }
            }
        }
    }

    // epilogue: thread holds c0(r=g,c=2tg) c1(c+1) c2(r+8) c3
    const int g = lane >> 2, tg = lane & 3;
#pragma unroll
    for (int mb = 0; mb < 2; mb++) {
        const int row0 = warp_m * 32 + mb * 16 + g;
        float* dbase = g_kallp + ((size_t)(b * 128 + row0)) * LAYER_R + (size_t)m * 128;
#pragma unroll
        for (int nb = 0; nb < 8; nb++) {
            const int col = warp_n * 64 + nb * 8 + tg * 2;
            const float b0 = sbias[col], b1 = sbias[col + 1];
            float2 v0 = make_float2(acc[mb][nb][0] + b0, acc[mb][nb][1] + b1);
            float2 v1 = make_float2(acc[mb][nb][2] + b0, acc[mb][nb][3] + b1);
            *(float2*)(dbase + col) = v0;
            *(float2*)(dbase + (size_t)8 * LAYER_R + col) = v1;
        }
    }
}

// ---------------- LVC layer: g_hA -> g_hB, f32x2 packed along o ----------------
__global__ void __launch_bounds__(256, 2) k_lvc(int layer) {
    __shared__ __align__(16) float hs[64][132];
    __shared__ __align__(16) float As[24][128];

    const int sh = blockIdx.x, l = blockIdx.y, b = blockIdx.z;
    const int t0 = l * HOPSZ + sh * 128;
    const int tid = threadIdx.x;
    const int wid = tid >> 5, lane = tid & 31;
    const long hb = (long)b * HID * T_LEN;

    const float* kerb = g_kallp + ((long)(b * LC + l)) * LAYER_R;
    unsigned long long acc2[4][8];
#pragma unroll
    for (int i = 0; i < 4; i++)
#pragma unroll
        for (int j = 0; j < 8; j++) acc2[i][j] = 0ULL;

    const int ri = tid & 15, li = tid >> 4;
    const int o0 = ri * 8, s0 = li * 8;

    for (int cpass = 0; cpass < 2; cpass++) {
        __syncthreads();
        const int c0 = cpass * 64;
        for (int i = wid; i < 64; i += 8) {
            const float* src = g_hA + hb + (long)(c0 + i) * T_LEN;
            for (int tt = lane; tt < 130; tt += 32) {
                int t = t0 - 1 + tt;
                hs[i][tt] = (t >= 0 && t < T_LEN) ? src[t] : 0.f;
            }
        }
        for (int it = 0; it < 8; it++) {
            __syncthreads();
#pragma unroll
            for (int f4 = 0; f4 < 3; f4++) {
                int f = tid + 256 * f4;
                *(float4*)&As[f >> 5][(f & 31) << 2] =
                    *(const float4*)(kerb + (cpass * 8 + it) * 3072 + (f << 2));
            }
            __syncthreads();
#pragma unroll
            for (int di = 0; di < 8; di++) {
                const float* hrow = &hs[it * 8 + di][s0];
                unsigned long long wd[10];
#pragma unroll
                for (int j = 0; j < 10; j++) { float t = hrow[j]; DUP2(wd[j], t); }
#pragma unroll
                for (int k = 0; k < 3; k++) {
                    const ulonglong2 a01 = *(const ulonglong2*)&As[di * 3 + k][o0];
                    const ulonglong2 a23 = *(const ulonglong2*)&As[di * 3 + k][o0 + 4];
#pragma unroll
                    for (int si = 0; si < 8; si++) {
                        FMA2(acc2[0][si], a01.x, wd[k + si]);
                        FMA2(acc2[1][si], a01.y, wd[k + si]);
                        FMA2(acc2[2][si], a23.x, wd[k + si]);
                        FMA2(acc2[3][si], a23.y, wd[k + si]);
                    }
                }
            }
        }
    }

    const float* bb = g_ballT + ((long)(b * LC + l)) * 512 + layer * HID;
#pragma unroll
    for (int oi2 = 0; oi2 < 4; oi2++) {
        float rlo[8], rhi[8];
#pragma unroll
        for (int si = 0; si < 8; si++) UNPK2(rlo[si], rhi[si], acc2[oi2][si]);
        const int oa = o0 + 2 * oi2, ob = oa + 1;
        const float bva = bb[oa], bvb = bb[ob];
        float* da = g_hB + hb + (long)oa * T_LEN + t0 + s0;
        float* db2 = g_hB + hb + (long)ob * T_LEN + t0 + s0;
        float4 v0, v1;
        {float u=rlo[0]+bva; v0.x=u>=0.f?u:3.f*u;} {float u=rlo[1]+bva; v0.y=u>=0.f?u:3.f*u;}
        {float u=rlo[2]+bva; v0.z=u>=0.f?u:3.f*u;} {float u=rlo[3]+bva; v0.w=u>=0.f?u:3.f*u;}
        {float u=rlo[4]+bva; v1.x=u>=0.f?u:3.f*u;} {float u=rlo[5]+bva; v1.y=u>=0.f?u:3.f*u;}
        {float u=rlo[6]+bva; v1.z=u>=0.f?u:3.f*u;} {float u=rlo[7]+bva; v1.w=u>=0.f?u:3.f*u;}
        *(float4*)da = v0; *(float4*)(da + 4) = v1;
        {float u=rhi[0]+bvb; v0.x=u>=0.f?u:3.f*u;} {float u=rhi[1]+bvb; v0.y=u>=0.f?u:3.f*u;}
        {float u=rhi[2]+bvb; v0.z=u>=0.f?u:3.f*u;} {float u=rhi[3]+bvb; v0.w=u>=0.f?u:3.f*u;}
        {float u=rhi[4]+bvb; v1.x=u>=0.f?u:3.f*u;} {float u=rhi[5]+bvb; v1.y=u>=0.f?u:3.f*u;}
        {float u=rhi[6]+bvb; v1.z=u>=0.f?u:3.f*u;} {float u=rhi[7]+bvb; v1.w=u>=0.f?u:3.f*u;}
        *(float4*)db2 = v0; *(float4*)(db2 + 4) = v1;
    }
}

// ---------------- dilated conv layer: g_hB -> g_hA, f32x2 packed along o ----------------
__global__ void __launch_bounds__(256, 2) k_dil(const float* __restrict__ bbias,
                                                int layer, int d) {
    __shared__ __align__(16) float hs[32][184];
    __shared__ __align__(16) float As[24][128];

    const int tb = blockIdx.x, b = blockIdx.y;
    const int t0 = tb * 128;
    const int W = 128 + 2 * d;
    const int tid = threadIdx.x, wid = tid >> 5, lane = tid & 31;
    const long hb = (long)b * HID * T_LEN;

    const float* wb = g_wT + (long)layer * LAYER_R;
    unsigned long long acc2[4][8];
#pragma unroll
    for (int i = 0; i < 4; i++)
#pragma unroll
        for (int j = 0; j < 8; j++) acc2[i][j] = 0ULL;

    const int ri = tid & 15, li = tid >> 4;
    const int o0 = ri * 8, s0 = li * 8;

    for (int cpass = 0; cpass < 4; cpass++) {
        __syncthreads();
        const int c0 = cpass * 32;
        for (int i = wid; i < 32; i += 8) {
            const float* src = g_hB + hb + (long)(c0 + i) * T_LEN;
            for (int tt = lane; tt < W; tt += 32) {
                int t = t0 - d + tt;
                hs[i][tt] = (t >= 0 && t < T_LEN) ? src[t] : 0.f;
            }
        }
        for (int it = 0; it < 4; it++) {
            __syncthreads();
#pragma unroll
            for (int f4 = 0; f4 < 3; f4++) {
                int f = tid + 256 * f4;
                *(float4*)&As[f >> 5][(f & 31) << 2] =
                    *(const float4*)(wb + (cpass * 4 + it) * 3072 + (f << 2));
            }
            __syncthreads();
#pragma unroll
            for (int di = 0; di < 8; di++) {
                const float* hrow = &hs[it * 8 + di][s0];
#pragma unroll
                for (int k = 0; k < 3; k++) {
                    unsigned long long wd[8];
#pragma unroll
                    for (int j = 0; j < 8; j++) { float t = hrow[k * d + j]; DUP2(wd[j], t); }
                    const ulonglong2 a01 = *(const ulonglong2*)&As[di * 3 + k][o0];
                    const ulonglong2 a23 = *(const ulonglong2*)&As[di * 3 + k][o0 + 4];
#pragma unroll
                    for (int si = 0; si < 8; si++) {
                        FMA2(acc2[0][si], a01.x, wd[si]);
                        FMA2(acc2[1][si], a01.y, wd[si]);
                        FMA2(acc2[2][si], a23.x, wd[si]);
                        FMA2(acc2[3][si], a23.y, wd[si]);
                    }
                }
            }
        }
    }

#pragma unroll
    for (int oi2 = 0; oi2 < 4; oi2++) {
        float rlo[8], rhi[8];
#pragma unroll
        for (int si = 0; si < 8; si++) UNPK2(rlo[si], rhi[si], acc2[oi2][si]);
        const int oa = o0 + 2 * oi2, ob = oa + 1;
        const float bva = bbias[layer * HID + oa], bvb = bbias[layer * HID + ob];
        float* da = g_hA + hb + (long)oa * T_LEN + t0 + s0;
        float* db2 = g_hA + hb + (long)ob * T_LEN + t0 + s0;
        float4 v0, v1;
        {float u=rlo[0]+bva; v0.x=u>=0.f?u:3.f*u;} {float u=rlo[1]+bva; v0.y=u>=0.f?u:3.f*u;}
        {float u=rlo[2]+bva; v0.z=u>=0.f?u:3.f*u;} {float u=rlo[3]+bva; v0.w=u>=0.f?u:3.f*u;}
        {float u=rlo[4]+bva; v1.x=u>=0.f?u:3.f*u;} {float u=rlo[5]+bva; v1.y=u>=0.f?u:3.f*u;}
        {float u=rlo[6]+bva; v1.z=u>=0.f?u:3.f*u;} {float u=rlo[7]+bva; v1.w=u>=0.f?u:3.f*u;}
        *(float4*)da = v0; *(float4*)(da + 4) = v1;
        {float u=rhi[0]+bvb; v0.x=u>=0.f?u:3.f*u;} {float u=rhi[1]+bvb; v0.y=u>=0.f?u:3.f*u;}
        {float u=rhi[2]+bvb; v0.z=u>=0.f?u:3.f*u;} {float u=rhi[3]+bvb; v0.w=u>=0.f?u:3.f*u;}
        {float u=rhi[4]+bvb; v1.x=u>=0.f?u:3.f*u;} {float u=rhi[5]+bvb; v1.y=u>=0.f?u:3.f*u;}
        {float u=rhi[6]+bvb; v1.z=u>=0.f?u:3.f*u;} {float u=rhi[7]+bvb; v1.w=u>=0.f?u:3.f*u;}
        *(float4*)db2 = v0; *(float4*)(db2 + 4) = v1;
    }
}

// ---------------- postconv ----------------
__global__ void k_post(const float* __restrict__ pw, const float* __restrict__ pb,
                       float* __restrict__ out) {
    __shared__ float wsh[128];
    const int b = blockIdx.y;
    const int t = blockIdx.x * 256 + threadIdx.x;
    if (threadIdx.x < 128) wsh[threadIdx.x] = pw[threadIdx.x];
    __syncthreads();
    const float* hp = g_hA + (long)b * HID * T_LEN + t;
    float acc = pb[0];
#pragma unroll 8
    for (int ch = 0; ch < 128; ch++) acc += wsh[ch] * hp[(long)ch * T_LEN];
    out[(long)b * T_LEN + t] = acc;
}

// ---------------- launch ----------------
extern "C" void kernel_launch(void* const* d_in, const int* in_sizes, int n_in,
                              void* d_out, int out_size) {
    const float* x        = (const float*)d_in[0];
    const float* c        = (const float*)d_in[1];
    const float* kernel_w = (const float*)d_in[2];
    const float* kernel_b = (const float*)d_in[3];
    const float* biasp_w  = (const float*)d_in[4];
    const float* biasp_b  = (const float*)d_in[5];
    const float* pre_w    = (const float*)d_in[6];
    const float* pre_b    = (const float*)d_in[7];
    const float* block_w  = (const float*)d_in[8];
    const float* block_b  = (const float*)d_in[9];
    const float* post_w   = (const float*)d_in[10];
    const float* post_b   = (const float*)d_in[11];
    float* out = (float*)d_out;

    k_permw<<<768, 256>>>(block_w);
    k_pre<<<dim3(128, 512), 256>>>(x, pre_w, pre_b);
    k_biasp<<<dim3(512, 4), 128>>>(biasp_w, biasp_b, c);
    k_cvt_c<<<1024, 256>>>(c);
    k_cvt_kw<<<98304, 256>>>(kernel_w);

    const int dils[4] = {1, 3, 9, 27};
    for (int layer = 0; layer < 4; layer++) {
        k_mma_pred<<<dim3(4, 384), 256>>>(kernel_b, layer);
        k_lvc<<<dim3(2, 128, 4), 256>>>(layer);
        k_dil<<<dim3(256, 4), 256>>>(block_b, layer, dils[layer]);
    }
    k_post<<<dim3(128, 4), 256>>>(post_w, post_b, out);
}

// round 16
// speedup vs baseline: 1.4597x; 1.0778x over previous
#include <cuda_runtime.h>
#include <cuda_bf16.h>
#include <cstdint>

#define T_LEN   32768
#define B_SZ    4
#define HID     128
#define NL      4
#define KERS    3
#define CONDC   512
#define LC      128
#define NM      384     /* m-tiles per layer: o*3+k */
#define KSLICE  16384   /* 128*128 */
#define WSLICE  49152   /* 3*128*128 */

// ---------------- scratch (device globals; no allocation) ----------------
// bf16 hi/lo split of kernel_w, pre-permuted: [layer][m=(o,k)][i][c]
static __device__ __nv_bfloat16 g_kwhi[(size_t)NL * NM * HID * CONDC];
static __device__ __nv_bfloat16 g_kwlo[(size_t)NL * NM * HID * CONDC];
// bf16 hi/lo split of c, transposed: [b][l][cond]
static __device__ __nv_bfloat16 g_chi[B_SZ * LC * CONDC];
static __device__ __nv_bfloat16 g_clo[B_SZ * LC * CONDC];
// predicted kernels bf16 hi/lo: [b][l][k][o][i]
static __device__ unsigned short g_kerhi[(size_t)B_SZ * LC * WSLICE];
static __device__ unsigned short g_kerlo[(size_t)B_SZ * LC * WSLICE];
// dilated-conv weights bf16 hi/lo: [layer][k][o][i]
static __device__ unsigned short g_wThi[NL * WSLICE];
static __device__ unsigned short g_wTlo[NL * WSLICE];
// activations, time-major bf16 hi/lo: [b][t][ch]
static __device__ unsigned short g_hAhi[(size_t)B_SZ * T_LEN * HID];
static __device__ unsigned short g_hAlo[(size_t)B_SZ * T_LEN * HID];
static __device__ unsigned short g_hBhi[(size_t)B_SZ * T_LEN * HID];
static __device__ unsigned short g_hBlo[(size_t)B_SZ * T_LEN * HID];
// LVC biases [b][l][512]
static __device__ float g_ballT[B_SZ * LC * 512];

__device__ __forceinline__ unsigned short f2bf(float v) {
    return __bfloat16_as_ushort(__float2bfloat16(v));
}
__device__ __forceinline__ float bf2f(unsigned short u) {
    return __bfloat162float(__ushort_as_bfloat16(u));
}
__device__ __forceinline__ uint32_t smem_u32(const void* p) {
    uint32_t a;
    asm("{ .reg .u64 t; cvta.to.shared.u64 t, %1; cvt.u32.u64 %0, t; }" : "=r"(a) : "l"(p));
    return a;
}
__device__ __forceinline__ void ldmx4(uint32_t* r, uint32_t addr) {
    asm volatile("ldmatrix.sync.aligned.m8n8.x4.shared.b16 {%0,%1,%2,%3}, [%4];"
                 : "=r"(r[0]), "=r"(r[1]), "=r"(r[2]), "=r"(r[3]) : "r"(addr));
}
__device__ __forceinline__ void mma_bf16(float* c, const uint32_t* a, uint32_t b0, uint32_t b1) {
    asm volatile(
        "mma.sync.aligned.m16n8k16.row.col.f32.bf16.bf16.f32 "
        "{%0,%1,%2,%3}, {%4,%5,%6,%7}, {%8,%9}, {%0,%1,%2,%3};"
        : "+f"(c[0]), "+f"(c[1]), "+f"(c[2]), "+f"(c[3])
        : "r"(a[0]), "r"(a[1]), "r"(a[2]), "r"(a[3]), "r"(b0), "r"(b1));
}

// ---------------- setup: kernel_w fp32 -> permuted bf16 hi/lo ----------------
// permuted row (layer, m=(o*3+k), rr=i) <- orig row ((layer*128+i)*128+o)*3+k
__global__ void k_cvt_kw(const float* __restrict__ kw) {
    long g = (long)blockIdx.x * 256 + threadIdx.x;
    if (g >= (long)NL * NM * HID * (CONDC / 4)) return;
    int c4 = (int)(g & 127);
    long rowp = g >> 7;
    int rr = (int)(rowp & 127);                      // i
    int mm = (int)(rowp >> 7);
    int m = mm % NM, layer = mm / NM;
    int oo = m / 3, kk = m - oo * 3;
    long srow = (long)layer * WSLICE + (long)rr * 384 + oo * 3 + kk;
    float4 v = *(const float4*)(kw + srow * CONDC + c4 * 4);
    __nv_bfloat16 h0 = __float2bfloat16(v.x), h1 = __float2bfloat16(v.y);
    __nv_bfloat16 h2 = __float2bfloat16(v.z), h3 = __float2bfloat16(v.w);
    __nv_bfloat16 l0 = __float2bfloat16(v.x - __bfloat162float(h0));
    __nv_bfloat16 l1 = __float2bfloat16(v.y - __bfloat162float(h1));
    __nv_bfloat16 l2 = __float2bfloat16(v.z - __bfloat162float(h2));
    __nv_bfloat16 l3 = __float2bfloat16(v.w - __bfloat162float(h3));
    ushort4 uh = make_ushort4(__bfloat16_as_ushort(h0), __bfloat16_as_ushort(h1),
                              __bfloat16_as_ushort(h2), __bfloat16_as_ushort(h3));
    ushort4 ul = make_ushort4(__bfloat16_as_ushort(l0), __bfloat16_as_ushort(l1),
                              __bfloat16_as_ushort(l2), __bfloat16_as_ushort(l3));
    *(ushort4*)(g_kwhi + rowp * CONDC + c4 * 4) = uh;
    *(ushort4*)(g_kwlo + rowp * CONDC + c4 * 4) = ul;
}

// c fp32 [b][cond][l] -> bf16 hi/lo [b][l][cond]
__global__ void k_cvt_c(const float* __restrict__ cc) {
    int g = blockIdx.x * 256 + threadIdx.x;
    int l = g & 127, q = g >> 7;
    int cond = q & 511, b = q >> 9;
    float v = cc[((long)b * CONDC + cond) * LC + l];
    __nv_bfloat16 h = __float2bfloat16(v);
    __nv_bfloat16 lo = __float2bfloat16(v - __bfloat162float(h));
    g_chi[((long)b * LC + l) * CONDC + cond] = h;
    g_clo[((long)b * LC + l) * CONDC + cond] = lo;
}

// block_w (layer,o,i,k) fp32 -> bf16 hi/lo [layer][k][o][i]
__global__ void k_cvt_wT(const float* __restrict__ bw) {
    int s = blockIdx.x * 256 + threadIdx.x;
    if (s >= NL * HID * HID * KERS) return;
    int k = s % 3; int q = s / 3;
    int i = q % 128; q /= 128;
    int o = q % 128; int layer = q / 128;
    float v = bw[s];
    unsigned short hi = f2bf(v);
    unsigned short lo = f2bf(v - bf2f(hi));
    int dst = ((layer * 3 + k) * 128 + o) * 128 + i;
    g_wThi[dst] = hi; g_wTlo[dst] = lo;
}

// ---------------- preconv: x -> hA time-major bf16 hi/lo ----------------
__global__ void k_pre(const float* __restrict__ x, const float* __restrict__ pw,
                      const float* __restrict__ pb) {
    long idx = (long)blockIdx.x * 256 + threadIdx.x;   // b,t,ch
    int ch = (int)(idx & 127);
    long bt = idx >> 7;                                // b*T + t
    float v = pw[ch] * x[bt] + pb[ch];
    v = v >= 0.f ? v : 0.2f * v;
    unsigned short hi = f2bf(v);
    g_hAhi[idx] = hi;
    g_hAlo[idx] = f2bf(v - bf2f(hi));
}

// ---------------- bias predictor ----------------
__global__ void k_biasp(const float* __restrict__ bw, const float* __restrict__ bb,
                        const float* __restrict__ cc) {
    const int row = blockIdx.x, b = blockIdx.y;
    const int l = threadIdx.x;
    const float* cp = cc + (long)b * CONDC * LC + l;
    const float* wp = bw + (long)row * CONDC;
    float acc = bb[row];
#pragma unroll 8
    for (int c2 = 0; c2 < CONDC; c2++) acc += wp[c2] * cp[(long)c2 * LC];
    g_ballT[((long)(b * LC + l)) * 512 + row] = acc;
}

// ---------------- kernel-predictor GEMM via mma.sync (one layer) ----------------
// Tile m=(o*3+k): D[l][i] = sum_c c[b][l][c]*kw[layer,i,o,k][c] + kb; write bf16 hi/lo
// into g_ker[b][l][k][o][i].
__global__ void __launch_bounds__(256, 2)
k_mma_pred(const float* __restrict__ kb, int layer) {
    __shared__ __align__(1024) __nv_bfloat16 sA[128 * 64]; // 16 KB, SW128
    __shared__ __align__(1024) __nv_bfloat16 sB[128 * 64]; // 16 KB
    __shared__ float sbias[128];

    const int b = blockIdx.x, m = blockIdx.y;
    const int tid = threadIdx.x, lane = tid & 31, wid = tid >> 5;
    const int warp_m = wid >> 1, warp_n = wid & 1;
    const int oo = m / 3, kk = m - oo * 3;

    if (tid < 128) sbias[tid] = kb[(long)layer * WSLICE + (long)tid * 384 + oo * 3 + kk];

    const __nv_bfloat16* aHi = g_chi + (size_t)b * 128 * CONDC;
    const __nv_bfloat16* aLo = g_clo + (size_t)b * 128 * CONDC;
    const __nv_bfloat16* bHi = g_kwhi + (size_t)(layer * NM + m) * 128 * CONDC;
    const __nv_bfloat16* bLo = g_kwlo + (size_t)(layer * NM + m) * 128 * CONDC;

    float acc[2][8][4];
#pragma unroll
    for (int i = 0; i < 2; i++)
#pragma unroll
        for (int j = 0; j < 8; j++)
#pragma unroll
            for (int k = 0; k < 4; k++) acc[i][j][k] = 0.f;

    const uint32_t sAu = smem_u32(sA), sBu = smem_u32(sB);
    const int at = lane >> 3;
    const int a_row = warp_m * 32 + (at & 1) * 8 + (lane & 7);
    const int a_kb  = (at >> 1) * 16;
    const int b_row = warp_n * 64 + (at >> 1) * 8 + (lane & 7);
    const int b_kb  = (at & 1) * 16;

    for (int term = 0; term < 3; term++) {
        const __nv_bfloat16* srcA = (term == 2) ? aLo : aHi;
        const __nv_bfloat16* srcB = (term == 1) ? bLo : bHi;
#pragma unroll 1
        for (int chunk = 0; chunk < 8; chunk++) {
            const int c0 = chunk * 64;
            __syncthreads();
            for (int q = tid; q < 2048; q += 256) {
                int tile = q >> 10, qq = q & 1023;
                int rr = qq >> 3, c8 = qq & 7;
                uint32_t off = rr * 128 + c8 * 16;
                uint32_t sw = off ^ ((off >> 3) & 0x70);
                const __nv_bfloat16* src = (tile ? srcB : srcA) + (size_t)rr * CONDC + c0 + c8 * 8;
                *(uint4*)((char*)(tile ? sB : sA) + sw) = *(const uint4*)src;
            }
            __syncthreads();
#pragma unroll
            for (int s = 0; s < 4; s++) {
                uint32_t aF[2][4];
#pragma unroll
                for (int mb = 0; mb < 2; mb++) {
                    int row = a_row + mb * 16;
                    int kbyte = (a_kb + s * 32) ^ ((row & 7) << 4);
                    ldmx4(aF[mb], sAu + row * 128 + kbyte);
                }
                uint32_t bF[4][4];
#pragma unroll
                for (int j2 = 0; j2 < 4; j2++) {
                    int row = b_row + j2 * 16;
                    int kbyte = (b_kb + s * 32) ^ ((row & 7) << 4);
                    ldmx4(bF[j2], sBu + row * 128 + kbyte);
                }
#pragma unroll
                for (int mb = 0; mb < 2; mb++)
#pragma unroll
                    for (int j2 = 0; j2 < 4; j2++) {
                        mma_bf16(acc[mb][2 * j2],     aF[mb], bF[j2][0], bF[j2][1]);
                        mma_bf16(acc[mb][2 * j2 + 1], aF[mb], bF[j2][2], bF[j2][3]);
                    }
            }
        }
    }

    // epilogue: rows = l, cols = i -> g_ker[b][l][kk][oo][i] bf16 hi/lo
    const int g = lane >> 2, tg = lane & 3;
#pragma unroll
    for (int mb = 0; mb < 2; mb++) {
        const int l0 = warp_m * 32 + mb * 16 + g;
        const size_t base0 = ((size_t)((b * 128 + l0) * 3 + kk) * 128 + oo) * 128;
        const size_t base1 = ((size_t)((b * 128 + l0 + 8) * 3 + kk) * 128 + oo) * 128;
#pragma unroll
        for (int nb = 0; nb < 8; nb++) {
            const int col = warp_n * 64 + nb * 8 + tg * 2;
            const float b0 = sbias[col], b1 = sbias[col + 1];
            float v0 = acc[mb][nb][0] + b0, v1 = acc[mb][nb][1] + b1;
            float v2 = acc[mb][nb][2] + b0, v3 = acc[mb][nb][3] + b1;
            unsigned short h0 = f2bf(v0), h1 = f2bf(v1), h2 = f2bf(v2), h3 = f2bf(v3);
            *(ushort2*)(g_kerhi + base0 + col) = make_ushort2(h0, h1);
            *(ushort2*)(g_kerlo + base0 + col) = make_ushort2(f2bf(v0 - bf2f(h0)), f2bf(v1 - bf2f(h1)));
            *(ushort2*)(g_kerhi + base1 + col) = make_ushort2(h2, h3);
            *(ushort2*)(g_kerlo + base1 + col) = make_ushort2(f2bf(v2 - bf2f(h2)), f2bf(v3 - bf2f(h3)));
        }
    }
}

// ---------------- unified conv (LVC d=1 with predicted ker, or dilated with wT) ----------------
// D[t][o] = leaky3( sum_{k,i} h[t + (k-1)*d][i] * W[slice][k][o][i] + bias[o] )
// M=64 t-rows x N=128 o-cols, K = 3k x 128i, 3-term bf16 hi/lo split.
// Scratch buffers selected IN-KERNEL from isLvc; blockb is a real device pointer.
__global__ void __launch_bounds__(256, 2)
k_conv(const float* __restrict__ blockb, int d, int isLvc, int layer) {
    __shared__ __align__(1024) unsigned short sA[2][120][64]; // 30 KB (118 rows used)
    __shared__ __align__(1024) unsigned short sB[128][64];    // 16 KB
    __shared__ float sbias[128];

    const int tb = blockIdx.x, b = blockIdx.y;
    const int t0 = tb * 64;
    const int tid = threadIdx.x, lane = tid & 31, wid = tid >> 5;
    const int warp_m = wid >> 1, warp_n = wid & 1;   // 4 x 2: 16 t-rows, 64 o-cols per warp

    const unsigned short* srcHi = isLvc ? g_hAhi : g_hBhi;
    const unsigned short* srcLo = isLvc ? g_hAlo : g_hBlo;
    unsigned short* dstHi       = isLvc ? g_hBhi : g_hAhi;
    unsigned short* dstLo       = isLvc ? g_hBlo : g_hAlo;
    const unsigned short* wHi   = isLvc ? g_kerhi : g_wThi;
    const unsigned short* wLo   = isLvc ? g_kerlo : g_wTlo;

    const int slice = isLvc ? (b * 128 + (t0 >> 8)) : layer;
    const float* bias = isLvc ? g_ballT + (size_t)(b * 128 + (t0 >> 8)) * 512 + layer * 128
                              : blockb + layer * 128;
    if (tid < 128) sbias[tid] = bias[tid];

    const int nrows = 64 + 2 * d;                    // <= 118
    const size_t hbase = (size_t)b * T_LEN * 128;

    float acc[8][4];
#pragma unroll
    for (int j = 0; j < 8; j++)
#pragma unroll
        for (int k = 0; k < 4; k++) acc[j][k] = 0.f;

    const uint32_t sAu = smem_u32(sA), sBu = smem_u32(sB);
    const int at = lane >> 3;
    const int a_row0 = warp_m * 16 + (at & 1) * 8 + (lane & 7);
    const int a_kb   = (at >> 1) * 16;
    const int b_row  = warp_n * 64 + (at >> 1) * 8 + (lane & 7);
    const int b_kb   = (at & 1) * 16;

#pragma unroll 1
    for (int av = 0; av < 2; av++) {                 // A variant: 0=hi, 1=lo
        const unsigned short* srcA = av ? srcLo : srcHi;
        __syncthreads();                             // prior compute done with sA
        {
            const int nq = nrows * 8;                // uint4 units per half
            for (int q = tid; q < 2 * nq; q += 256) {
                int h = q / nq, rem = q - h * nq;
                int row = rem >> 3, c8 = rem & 7;
                int t = t0 - d + row;
                uint4 v = make_uint4(0, 0, 0, 0);
                if (t >= 0 && t < T_LEN)
                    v = *(const uint4*)(srcA + hbase + (size_t)t * 128 + h * 64 + c8 * 8);
                uint32_t off = row * 128 + c8 * 16;
                uint32_t sw = off ^ ((off >> 3) & 0x70);
                *(uint4*)((char*)sA + h * 15360 + sw) = v;
            }
        }
        const int nbv = av ? 1 : 2;                  // hi pairs with Bhi+Blo; lo with Bhi
#pragma unroll 1
        for (int k = 0; k < 3; k++) {
#pragma unroll 1
            for (int h = 0; h < 2; h++) {
#pragma unroll 1
                for (int bv = 0; bv < nbv; bv++) {
                    const unsigned short* srcB = bv ? wLo : wHi;
                    __syncthreads();
                    for (int q = tid; q < 1024; q += 256) {
                        int row = q >> 3, c8 = q & 7;
                        uint4 v = *(const uint4*)(srcB + (size_t)slice * WSLICE +
                                                  k * KSLICE + row * 128 + h * 64 + c8 * 8);
                        uint32_t off = row * 128 + c8 * 16;
                        uint32_t sw = off ^ ((off >> 3) & 0x70);
                        *(uint4*)((char*)sB + sw) = v;
                    }
                    __syncthreads();
#pragma unroll
                    for (int s = 0; s < 4; s++) {
                        uint32_t aF[4];
                        {
                            int row = a_row0 + k * d;
                            int kbyte = (a_kb + s * 32) ^ ((row & 7) << 4);
                            ldmx4(aF, sAu + h * 15360 + row * 128 + kbyte);
                        }
                        uint32_t bF[4][4];
#pragma unroll
                        for (int j2 = 0; j2 < 4; j2++) {
                            int row = b_row + j2 * 16;
                            int kbyte = (b_kb + s * 32) ^ ((row & 7) << 4);
                            ldmx4(bF[j2], sBu + row * 128 + kbyte);
                        }
#pragma unroll
                        for (int j2 = 0; j2 < 4; j2++) {
                            mma_bf16(acc[2 * j2],     aF, bF[j2][0], bF[j2][1]);
                            mma_bf16(acc[2 * j2 + 1], aF, bF[j2][2], bF[j2][3]);
                        }
                    }
                }
            }
        }
    }

    // epilogue: rows = t, cols = o; bias + leaky(3) + bf16 hi/lo split, time-major store
    const int g = lane >> 2, tg = lane & 3;
    const size_t r0 = hbase + (size_t)(t0 + warp_m * 16 + g) * 128;
    const size_t r1 = r0 + 8 * 128;
#pragma unroll
    for (int nb = 0; nb < 8; nb++) {
        const int col = warp_n * 64 + nb * 8 + tg * 2;
        const float b0 = sbias[col], b1 = sbias[col + 1];
        float v0 = acc[nb][0] + b0, v1 = acc[nb][1] + b1;
        float v2 = acc[nb][2] + b0, v3 = acc[nb][3] + b1;
        v0 = v0 >= 0.f ? v0 : 3.f * v0;  v1 = v1 >= 0.f ? v1 : 3.f * v1;
        v2 = v2 >= 0.f ? v2 : 3.f * v2;  v3 = v3 >= 0.f ? v3 : 3.f * v3;
        unsigned short h0 = f2bf(v0), h1 = f2bf(v1), h2 = f2bf(v2), h3 = f2bf(v3);
        *(ushort2*)(dstHi + r0 + col) = make_ushort2(h0, h1);
        *(ushort2*)(dstLo + r0 + col) = make_ushort2(f2bf(v0 - bf2f(h0)), f2bf(v1 - bf2f(h1)));
        *(ushort2*)(dstHi + r1 + col) = make_ushort2(h2, h3);
        *(ushort2*)(dstLo + r1 + col) = make_ushort2(f2bf(v2 - bf2f(h2)), f2bf(v3 - bf2f(h3)));
    }
}

// ---------------- postconv: out[b][t] = post_w . (hi+lo) + post_b ----------------
__global__ void k_post(const float* __restrict__ pw, const float* __restrict__ pb,
                       float* __restrict__ out) {
    __shared__ float wsh[128];
    const int b = blockIdx.y;
    const int t = blockIdx.x * 256 + threadIdx.x;
    if (threadIdx.x < 128) wsh[threadIdx.x] = pw[threadIdx.x];
    __syncthreads();
    const size_t base = ((size_t)b * T_LEN + t) * 128;
    float acc = pb[0];
#pragma unroll 4
    for (int c8 = 0; c8 < 16; c8++) {
        uint4 uh = *(const uint4*)(g_hAhi + base + c8 * 8);
        uint4 ul = *(const uint4*)(g_hAlo + base + c8 * 8);
        const uint32_t* ph = (const uint32_t*)&uh;
        const uint32_t* pl = (const uint32_t*)&ul;
#pragma unroll
        for (int w = 0; w < 4; w++) {
            float f0 = bf2f((unsigned short)(ph[w] & 0xffff)) + bf2f((unsigned short)(pl[w] & 0xffff));
            float f1 = bf2f((unsigned short)(ph[w] >> 16))    + bf2f((unsigned short)(pl[w] >> 16));
            acc += f0 * wsh[c8 * 8 + w * 2] + f1 * wsh[c8 * 8 + w * 2 + 1];
        }
    }
    out[(size_t)b * T_LEN + t] = acc;
}

// ---------------- launch ----------------
extern "C" void kernel_launch(void* const* d_in, const int* in_sizes, int n_in,
                              void* d_out, int out_size) {
    const float* x        = (const float*)d_in[0];
    const float* c        = (const float*)d_in[1];
    const float* kernel_w = (const float*)d_in[2];
    const float* kernel_b = (const float*)d_in[3];
    const float* biasp_w  = (const float*)d_in[4];
    const float* biasp_b  = (const float*)d_in[5];
    const float* pre_w    = (const float*)d_in[6];
    const float* pre_b    = (const float*)d_in[7];
    const float* block_w  = (const float*)d_in[8];
    const float* block_b  = (const float*)d_in[9];
    const float* post_w   = (const float*)d_in[10];
    const float* post_b   = (const float*)d_in[11];
    float* out = (float*)d_out;

    k_pre<<<65536, 256>>>(x, pre_w, pre_b);
    k_biasp<<<dim3(512, 4), 128>>>(biasp_w, biasp_b, c);
    k_cvt_c<<<1024, 256>>>(c);
    k_cvt_wT<<<768, 256>>>(block_w);
    k_cvt_kw<<<98304, 256>>>(kernel_w);

    const int dils[4] = {1, 3, 9, 27};
    for (int layer = 0; layer < 4; layer++) {
        k_mma_pred<<<dim3(4, 384), 256>>>(kernel_b, layer);
        k_conv<<<dim3(512, 4), 256>>>(block_b, 1, 1, layer);            // LVC: hA -> hB
        k_conv<<<dim3(512, 4), 256>>>(block_b, dils[layer], 0, layer);  // dil: hB -> hA
    }
    k_post<<<dim3(128, 4), 256>>>(post_w, post_b, out);
}

// round 17
// speedup vs baseline: 2.0024x; 1.3718x over previous
#include <cuda_runtime.h>
#include <cuda_bf16.h>
#include <cstdint>

#define T_LEN   32768
#define B_SZ    4
#define HID     128
#define NL      4
#define KERS    3
#define CONDC   512
#define LC      128
#define NM      384     /* m-tiles per layer: o*3+k */
#define KSLICE  16384   /* 128*128 */
#define WSLICE  49152   /* 3*128*128 */

// ---------------- scratch (device globals; no allocation) ----------------
static __device__ __nv_bfloat16 g_kwhi[(size_t)NL * NM * HID * CONDC];
static __device__ __nv_bfloat16 g_kwlo[(size_t)NL * NM * HID * CONDC];
static __device__ __nv_bfloat16 g_chi[B_SZ * LC * CONDC];
static __device__ __nv_bfloat16 g_clo[B_SZ * LC * CONDC];
static __device__ unsigned short g_kerhi[(size_t)B_SZ * LC * WSLICE];
static __device__ unsigned short g_kerlo[(size_t)B_SZ * LC * WSLICE];
static __device__ unsigned short g_wThi[NL * WSLICE];
static __device__ unsigned short g_wTlo[NL * WSLICE];
static __device__ unsigned short g_hAhi[(size_t)B_SZ * T_LEN * HID];
static __device__ unsigned short g_hAlo[(size_t)B_SZ * T_LEN * HID];
static __device__ unsigned short g_hBhi[(size_t)B_SZ * T_LEN * HID];
static __device__ unsigned short g_hBlo[(size_t)B_SZ * T_LEN * HID];
static __device__ float g_ballT[B_SZ * LC * 512];

__device__ __forceinline__ unsigned short f2bf(float v) {
    return __bfloat16_as_ushort(__float2bfloat16(v));
}
__device__ __forceinline__ float bf2f(unsigned short u) {
    return __bfloat162float(__ushort_as_bfloat16(u));
}
__device__ __forceinline__ uint32_t smem_u32(const void* p) {
    uint32_t a;
    asm("{ .reg .u64 t; cvta.to.shared.u64 t, %1; cvt.u32.u64 %0, t; }" : "=r"(a) : "l"(p));
    return a;
}
__device__ __forceinline__ void ldmx4(uint32_t* r, uint32_t addr) {
    asm volatile("ldmatrix.sync.aligned.m8n8.x4.shared.b16 {%0,%1,%2,%3}, [%4];"
                 : "=r"(r[0]), "=r"(r[1]), "=r"(r[2]), "=r"(r[3]) : "r"(addr));
}
__device__ __forceinline__ void mma_bf16(float* c, const uint32_t* a, uint32_t b0, uint32_t b1) {
    asm volatile(
        "mma.sync.aligned.m16n8k16.row.col.f32.bf16.bf16.f32 "
        "{%0,%1,%2,%3}, {%4,%5,%6,%7}, {%8,%9}, {%0,%1,%2,%3};"
        : "+f"(c[0]), "+f"(c[1]), "+f"(c[2]), "+f"(c[3])
        : "r"(a[0]), "r"(a[1]), "r"(a[2]), "r"(a[3]), "r"(b0), "r"(b1));
}
// cp.async (LDGSTS) helpers — baseline PTX, sm_80+
__device__ __forceinline__ void cp_async16(uint32_t saddr, const void* gaddr, int sz) {
    asm volatile("cp.async.cg.shared.global [%0], [%1], 16, %2;"
                 :: "r"(saddr), "l"(gaddr), "r"(sz) : "memory");
}
__device__ __forceinline__ void cp_commit() {
    asm volatile("cp.async.commit_group;" ::: "memory");
}
__device__ __forceinline__ void cp_wait1() {
    asm volatile("cp.async.wait_group 1;" ::: "memory");
}
__device__ __forceinline__ void cp_wait0() {
    asm volatile("cp.async.wait_group 0;" ::: "memory");
}

// ---------------- setup: kernel_w fp32 -> permuted bf16 hi/lo ----------------
__global__ void k_cvt_kw(const float* __restrict__ kw) {
    long g = (long)blockIdx.x * 256 + threadIdx.x;
    if (g >= (long)NL * NM * HID * (CONDC / 4)) return;
    int c4 = (int)(g & 127);
    long rowp = g >> 7;
    int rr = (int)(rowp & 127);                      // i
    int mm = (int)(rowp >> 7);
    int m = mm % NM, layer = mm / NM;
    int oo = m / 3, kk = m - oo * 3;
    long srow = (long)layer * WSLICE + (long)rr * 384 + oo * 3 + kk;
    float4 v = *(const float4*)(kw + srow * CONDC + c4 * 4);
    __nv_bfloat16 h0 = __float2bfloat16(v.x), h1 = __float2bfloat16(v.y);
    __nv_bfloat16 h2 = __float2bfloat16(v.z), h3 = __float2bfloat16(v.w);
    __nv_bfloat16 l0 = __float2bfloat16(v.x - __bfloat162float(h0));
    __nv_bfloat16 l1 = __float2bfloat16(v.y - __bfloat162float(h1));
    __nv_bfloat16 l2 = __float2bfloat16(v.z - __bfloat162float(h2));
    __nv_bfloat16 l3 = __float2bfloat16(v.w - __bfloat162float(h3));
    ushort4 uh = make_ushort4(__bfloat16_as_ushort(h0), __bfloat16_as_ushort(h1),
                              __bfloat16_as_ushort(h2), __bfloat16_as_ushort(h3));
    ushort4 ul = make_ushort4(__bfloat16_as_ushort(l0), __bfloat16_as_ushort(l1),
                              __bfloat16_as_ushort(l2), __bfloat16_as_ushort(l3));
    *(ushort4*)(g_kwhi + rowp * CONDC + c4 * 4) = uh;
    *(ushort4*)(g_kwlo + rowp * CONDC + c4 * 4) = ul;
}

__global__ void k_cvt_c(const float* __restrict__ cc) {
    int g = blockIdx.x * 256 + threadIdx.x;
    int l = g & 127, q = g >> 7;
    int cond = q & 511, b = q >> 9;
    float v = cc[((long)b * CONDC + cond) * LC + l];
    __nv_bfloat16 h = __float2bfloat16(v);
    __nv_bfloat16 lo = __float2bfloat16(v - __bfloat162float(h));
    g_chi[((long)b * LC + l) * CONDC + cond] = h;
    g_clo[((long)b * LC + l) * CONDC + cond] = lo;
}

__global__ void k_cvt_wT(const float* __restrict__ bw) {
    int s = blockIdx.x * 256 + threadIdx.x;
    if (s >= NL * HID * HID * KERS) return;
    int k = s % 3; int q = s / 3;
    int i = q % 128; q /= 128;
    int o = q % 128; int layer = q / 128;
    float v = bw[s];
    unsigned short hi = f2bf(v);
    unsigned short lo = f2bf(v - bf2f(hi));
    int dst = ((layer * 3 + k) * 128 + o) * 128 + i;
    g_wThi[dst] = hi; g_wTlo[dst] = lo;
}

// ---------------- preconv ----------------
__global__ void k_pre(const float* __restrict__ x, const float* __restrict__ pw,
                      const float* __restrict__ pb) {
    long idx = (long)blockIdx.x * 256 + threadIdx.x;
    int ch = (int)(idx & 127);
    long bt = idx >> 7;
    float v = pw[ch] * x[bt] + pb[ch];
    v = v >= 0.f ? v : 0.2f * v;
    unsigned short hi = f2bf(v);
    g_hAhi[idx] = hi;
    g_hAlo[idx] = f2bf(v - bf2f(hi));
}

// ---------------- bias predictor ----------------
__global__ void k_biasp(const float* __restrict__ bw, const float* __restrict__ bb,
                        const float* __restrict__ cc) {
    const int row = blockIdx.x, b = blockIdx.y;
    const int l = threadIdx.x;
    const float* cp = cc + (long)b * CONDC * LC + l;
    const float* wp = bw + (long)row * CONDC;
    float acc = bb[row];
#pragma unroll 8
    for (int c2 = 0; c2 < CONDC; c2++) acc += wp[c2] * cp[(long)c2 * LC];
    g_ballT[((long)(b * LC + l)) * 512 + row] = acc;
}

// ---------------- kernel-predictor GEMM via mma.sync (one layer) ----------------
__global__ void __launch_bounds__(256, 2)
k_mma_pred(const float* __restrict__ kb, int layer) {
    __shared__ __align__(1024) __nv_bfloat16 sA[128 * 64];
    __shared__ __align__(1024) __nv_bfloat16 sB[128 * 64];
    __shared__ float sbias[128];

    const int b = blockIdx.x, m = blockIdx.y;
    const int tid = threadIdx.x, lane = tid & 31, wid = tid >> 5;
    const int warp_m = wid >> 1, warp_n = wid & 1;
    const int oo = m / 3, kk = m - oo * 3;

    if (tid < 128) sbias[tid] = kb[(long)layer * WSLICE + (long)tid * 384 + oo * 3 + kk];

    const __nv_bfloat16* aHi = g_chi + (size_t)b * 128 * CONDC;
    const __nv_bfloat16* aLo = g_clo + (size_t)b * 128 * CONDC;
    const __nv_bfloat16* bHi = g_kwhi + (size_t)(layer * NM + m) * 128 * CONDC;
    const __nv_bfloat16* bLo = g_kwlo + (size_t)(layer * NM + m) * 128 * CONDC;

    float acc[2][8][4];
#pragma unroll
    for (int i = 0; i < 2; i++)
#pragma unroll
        for (int j = 0; j < 8; j++)
#pragma unroll
            for (int k = 0; k < 4; k++) acc[i][j][k] = 0.f;

    const uint32_t sAu = smem_u32(sA), sBu = smem_u32(sB);
    const int at = lane >> 3;
    const int a_row = warp_m * 32 + (at & 1) * 8 + (lane & 7);
    const int a_kb  = (at >> 1) * 16;
    const int b_row = warp_n * 64 + (at >> 1) * 8 + (lane & 7);
    const int b_kb  = (at & 1) * 16;

    for (int term = 0; term < 3; term++) {
        const __nv_bfloat16* srcA = (term == 2) ? aLo : aHi;
        const __nv_bfloat16* srcB = (term == 1) ? bLo : bHi;
#pragma unroll 1
        for (int chunk = 0; chunk < 8; chunk++) {
            const int c0 = chunk * 64;
            __syncthreads();
            for (int q = tid; q < 2048; q += 256) {
                int tile = q >> 10, qq = q & 1023;
                int rr = qq >> 3, c8 = qq & 7;
                uint32_t off = rr * 128 + c8 * 16;
                uint32_t sw = off ^ ((off >> 3) & 0x70);
                const __nv_bfloat16* src = (tile ? srcB : srcA) + (size_t)rr * CONDC + c0 + c8 * 8;
                *(uint4*)((char*)(tile ? sB : sA) + sw) = *(const uint4*)src;
            }
            __syncthreads();
#pragma unroll
            for (int s = 0; s < 4; s++) {
                uint32_t aF[2][4];
#pragma unroll
                for (int mb = 0; mb < 2; mb++) {
                    int row = a_row + mb * 16;
                    int kbyte = (a_kb + s * 32) ^ ((row & 7) << 4);
                    ldmx4(aF[mb], sAu + row * 128 + kbyte);
                }
                uint32_t bF[4][4];
#pragma unroll
                for (int j2 = 0; j2 < 4; j2++) {
                    int row = b_row + j2 * 16;
                    int kbyte = (b_kb + s * 32) ^ ((row & 7) << 4);
                    ldmx4(bF[j2], sBu + row * 128 + kbyte);
                }
#pragma unroll
                for (int mb = 0; mb < 2; mb++)
#pragma unroll
                    for (int j2 = 0; j2 < 4; j2++) {
                        mma_bf16(acc[mb][2 * j2],     aF[mb], bF[j2][0], bF[j2][1]);
                        mma_bf16(acc[mb][2 * j2 + 1], aF[mb], bF[j2][2], bF[j2][3]);
                    }
            }
        }
    }

    const int g = lane >> 2, tg = lane & 3;
#pragma unroll
    for (int mb = 0; mb < 2; mb++) {
        const int l0 = warp_m * 32 + mb * 16 + g;
        const size_t base0 = ((size_t)((b * 128 + l0) * 3 + kk) * 128 + oo) * 128;
        const size_t base1 = ((size_t)((b * 128 + l0 + 8) * 3 + kk) * 128 + oo) * 128;
#pragma unroll
        for (int nb = 0; nb < 8; nb++) {
            const int col = warp_n * 64 + nb * 8 + tg * 2;
            const float b0 = sbias[col], b1 = sbias[col + 1];
            float v0 = acc[mb][nb][0] + b0, v1 = acc[mb][nb][1] + b1;
            float v2 = acc[mb][nb][2] + b0, v3 = acc[mb][nb][3] + b1;
            unsigned short h0 = f2bf(v0), h1 = f2bf(v1), h2 = f2bf(v2), h3 = f2bf(v3);
            *(ushort2*)(g_kerhi + base0 + col) = make_ushort2(h0, h1);
            *(ushort2*)(g_kerlo + base0 + col) = make_ushort2(f2bf(v0 - bf2f(h0)), f2bf(v1 - bf2f(h1)));
            *(ushort2*)(g_kerhi + base1 + col) = make_ushort2(h2, h3);
            *(ushort2*)(g_kerlo + base1 + col) = make_ushort2(f2bf(v2 - bf2f(h2)), f2bf(v3 - bf2f(h3)));
        }
    }
}

// ---------------- unified conv, cp.async double-buffered ----------------
// D[t][o] = leaky3( sum_{k,i} h[t + (k-1)*d][i] * W[slice][k][o][i] + bias[o] )
// M=64 t x N=128 o; A slab = one (variant,half): rows t0-d..t0+63+d, 64 ch (128 B rows).
// B ring: 2 x 16 KB (128 o x 64 i).  Static smem total 48640 B (< 48 KB).
__global__ void __launch_bounds__(256, 2)
k_conv(const float* __restrict__ blockb, int d, int isLvc, int layer) {
    __shared__ __align__(1024) unsigned short sA[120 * 64];     // 15 KB
    __shared__ __align__(1024) unsigned short sB[2][64 * 128];  // 32 KB
    __shared__ float sbias[128];

    const int tb = blockIdx.x, b = blockIdx.y;
    const int t0 = tb * 64;
    const int tid = threadIdx.x, lane = tid & 31, wid = tid >> 5;
    const int warp_m = wid >> 1, warp_n = wid & 1;

    const unsigned short* srcHi = isLvc ? g_hAhi : g_hBhi;
    const unsigned short* srcLo = isLvc ? g_hAlo : g_hBlo;
    unsigned short* dstHi       = isLvc ? g_hBhi : g_hAhi;
    unsigned short* dstLo       = isLvc ? g_hBlo : g_hAlo;
    const unsigned short* wHi   = isLvc ? g_kerhi : g_wThi;
    const unsigned short* wLo   = isLvc ? g_kerlo : g_wTlo;

    const int slice = isLvc ? (b * 128 + (t0 >> 8)) : layer;
    const float* bias = isLvc ? g_ballT + (size_t)(b * 128 + (t0 >> 8)) * 512 + layer * 128
                              : blockb + layer * 128;
    if (tid < 128) sbias[tid] = bias[tid];

    const int nrows = 64 + 2 * d;                    // <= 118
    const size_t hbase = (size_t)b * T_LEN * 128;

    float acc[8][4];
#pragma unroll
    for (int j = 0; j < 8; j++)
#pragma unroll
        for (int k = 0; k < 4; k++) acc[j][k] = 0.f;

    const uint32_t sAu = smem_u32(sA), sBu = smem_u32(sB);
    const int at = lane >> 3;
    const int a_row0 = warp_m * 16 + (at & 1) * 8 + (lane & 7);
    const int a_kb   = (at >> 1) * 16;
    const int b_row  = warp_n * 64 + (at >> 1) * 8 + (lane & 7);
    const int b_kb   = (at & 1) * 16;

#pragma unroll 1
    for (int av = 0; av < 2; av++) {
        const unsigned short* srcA = av ? srcLo : srcHi;
        const int nbv = av ? 1 : 2;                  // hi pairs with Whi+Wlo; lo with Whi
        const int nst = 3 * nbv;
#pragma unroll 1
        for (int h = 0; h < 2; h++) {
            __syncthreads();                         // prior compute done with sA/sB
            // --- issue A slab (one cp.async group) ---
            {
                const int nq = nrows * 8;
                for (int q = tid; q < nq; q += 256) {
                    int row = q >> 3, c8 = q & 7;
                    int t = t0 - d + row;
                    int valid = (t >= 0 && t < T_LEN) ? 16 : 0;
                    const unsigned short* g = srcA + hbase +
                        (size_t)(valid ? t : 0) * 128 + h * 64 + c8 * 8;
                    uint32_t off = row * 128 + c8 * 16;
                    uint32_t sw = off ^ ((off >> 3) & 0x70);
                    cp_async16(sAu + sw, g, valid);
                }
                cp_commit();
            }
            // --- preload B stage 0 ---
            {
                const unsigned short* srcB = wHi;    // st0: k=0, bv=0
                const unsigned short* gb = srcB + (size_t)slice * WSLICE + h * 64;
                for (int q = tid; q < 1024; q += 256) {
                    int row = q >> 3, c8 = q & 7;
                    uint32_t off = row * 128 + c8 * 16;
                    uint32_t sw = off ^ ((off >> 3) & 0x70);
                    cp_async16(sBu + sw, gb + row * 128 + c8 * 8, 16);
                }
                cp_commit();
            }
#pragma unroll 1
            for (int st = 0; st < nst; st++) {
                if (st + 1 < nst) {                  // issue next B stage into other buffer
                    int k2 = (st + 1) / nbv, bv2 = (st + 1) - k2 * nbv;
                    const unsigned short* srcB = bv2 ? wLo : wHi;
                    const unsigned short* gb = srcB + (size_t)slice * WSLICE + k2 * KSLICE + h * 64;
                    uint32_t bbase = sBu + ((st + 1) & 1) * 16384;
                    for (int q = tid; q < 1024; q += 256) {
                        int row = q >> 3, c8 = q & 7;
                        uint32_t off = row * 128 + c8 * 16;
                        uint32_t sw = off ^ ((off >> 3) & 0x70);
                        cp_async16(bbase + sw, gb + row * 128 + c8 * 8, 16);
                    }
                    cp_commit();
                    cp_wait1();
                } else {
                    cp_wait0();
                }
                __syncthreads();
                const int k = st / nbv;
                const uint32_t bufB = sBu + (st & 1) * 16384;
#pragma unroll
                for (int s = 0; s < 4; s++) {
                    uint32_t aF[4];
                    {
                        int row = a_row0 + k * d;
                        int kbyte = (a_kb + s * 32) ^ ((row & 7) << 4);
                        ldmx4(aF, sAu + row * 128 + kbyte);
                    }
                    uint32_t bF[4][4];
#pragma unroll
                    for (int j2 = 0; j2 < 4; j2++) {
                        int row = b_row + j2 * 16;
                        int kbyte = (b_kb + s * 32) ^ ((row & 7) << 4);
                        ldmx4(bF[j2], bufB + row * 128 + kbyte);
                    }
#pragma unroll
                    for (int j2 = 0; j2 < 4; j2++) {
                        mma_bf16(acc[2 * j2],     aF, bF[j2][0], bF[j2][1]);
                        mma_bf16(acc[2 * j2 + 1], aF, bF[j2][2], bF[j2][3]);
                    }
                }
                __syncthreads();
            }
        }
    }

    // epilogue: rows = t, cols = o; bias + leaky(3) + bf16 hi/lo split, time-major store
    const int g = lane >> 2, tg = lane & 3;
    const size_t r0 = hbase + (size_t)(t0 + warp_m * 16 + g) * 128;
    const size_t r1 = r0 + 8 * 128;
#pragma unroll
    for (int nb = 0; nb < 8; nb++) {
        const int col = warp_n * 64 + nb * 8 + tg * 2;
        const float b0 = sbias[col], b1 = sbias[col + 1];
        float v0 = acc[nb][0] + b0, v1 = acc[nb][1] + b1;
        float v2 = acc[nb][2] + b0, v3 = acc[nb][3] + b1;
        v0 = v0 >= 0.f ? v0 : 3.f * v0;  v1 = v1 >= 0.f ? v1 : 3.f * v1;
        v2 = v2 >= 0.f ? v2 : 3.f * v2;  v3 = v3 >= 0.f ? v3 : 3.f * v3;
        unsigned short h0 = f2bf(v0), h1 = f2bf(v1), h2 = f2bf(v2), h3 = f2bf(v3);
        *(ushort2*)(dstHi + r0 + col) = make_ushort2(h0, h1);
        *(ushort2*)(dstLo + r0 + col) = make_ushort2(f2bf(v0 - bf2f(h0)), f2bf(v1 - bf2f(h1)));
        *(ushort2*)(dstHi + r1 + col) = make_ushort2(h2, h3);
        *(ushort2*)(dstLo + r1 + col) = make_ushort2(f2bf(v2 - bf2f(h2)), f2bf(v3 - bf2f(h3)));
    }
}

// ---------------- postconv ----------------
__global__ void k_post(const float* __restrict__ pw, const float* __restrict__ pb,
                       float* __restrict__ out) {
    __shared__ float wsh[128];
    const int b = blockIdx.y;
    const int t = blockIdx.x * 256 + threadIdx.x;
    if (threadIdx.x < 128) wsh[threadIdx.x] = pw[threadIdx.x];
    __syncthreads();
    const size_t base = ((size_t)b * T_LEN + t) * 128;
    float acc = pb[0];
#pragma unroll 4
    for (int c8 = 0; c8 < 16; c8++) {
        uint4 uh = *(const uint4*)(g_hAhi + base + c8 * 8);
        uint4 ul = *(const uint4*)(g_hAlo + base + c8 * 8);
        const uint32_t* ph = (const uint32_t*)&uh;
        const uint32_t* pl = (const uint32_t*)&ul;
#pragma unroll
        for (int w = 0; w < 4; w++) {
            float f0 = bf2f((unsigned short)(ph[w] & 0xffff)) + bf2f((unsigned short)(pl[w] & 0xffff));
            float f1 = bf2f((unsigned short)(ph[w] >> 16))    + bf2f((unsigned short)(pl[w] >> 16));
            acc += f0 * wsh[c8 * 8 + w * 2] + f1 * wsh[c8 * 8 + w * 2 + 1];
        }
    }
    out[(size_t)b * T_LEN + t] = acc;
}

// ---------------- launch ----------------
extern "C" void kernel_launch(void* const* d_in, const int* in_sizes, int n_in,
                              void* d_out, int out_size) {
    const float* x        = (const float*)d_in[0];
    const float* c        = (const float*)d_in[1];
    const float* kernel_w = (const float*)d_in[2];
    const float* kernel_b = (const float*)d_in[3];
    const float* biasp_w  = (const float*)d_in[4];
    const float* biasp_b  = (const float*)d_in[5];
    const float* pre_w    = (const float*)d_in[6];
    const float* pre_b    = (const float*)d_in[7];
    const float* block_w  = (const float*)d_in[8];
    const float* block_b  = (const float*)d_in[9];
    const float* post_w   = (const float*)d_in[10];
    const float* post_b   = (const float*)d_in[11];
    float* out = (float*)d_out;

    k_pre<<<65536, 256>>>(x, pre_w, pre_b);
    k_biasp<<<dim3(512, 4), 128>>>(biasp_w, biasp_b, c);
    k_cvt_c<<<1024, 256>>>(c);
    k_cvt_wT<<<768, 256>>>(block_w);
    k_cvt_kw<<<98304, 256>>>(kernel_w);

    const int dils[4] = {1, 3, 9, 27};
    for (int layer = 0; layer < 4; layer++) {
        k_mma_pred<<<dim3(4, 384), 256>>>(kernel_b, layer);
        k_conv<<<dim3(512, 4), 256>>>(block_b, 1, 1, layer);            // LVC: hA -> hB
        k_conv<<<dim3(512, 4), 256>>>(block_b, dils[layer], 0, layer);  // dil: hB -> hA
    }
    k_post<<<dim3(128, 4), 256>>>(post_w, post_b, out);
}